// round 1
// baseline (speedup 1.0000x reference)
#include <cuda_runtime.h>
#include <math.h>

// ---------------- problem constants ----------------
#define TOK   2048          // B*T*HP*WP
#define TWO_D 512
#define DDIM  256
#define KCONV 4608          // 512*9
#define TSTEPS 8

// ---------------- device scratch (no allocs allowed) ----------------
__device__ float g_xp [TOK*1024];
__device__ float g_z  [TOK*TWO_D];
__device__ float g_zn [TOK*TWO_D];
__device__ float g_col[TOK*KCONV];
__device__ float g_x  [TOK*TWO_D];
__device__ float g_xe [TOK*TWO_D];
__device__ float g_h  [TOK*TWO_D];
__device__ float g_xo [TOK*TWO_D];
__device__ float g_xn [TOK*TWO_D];
__device__ float g_hid[TOK*1024];
__device__ float g_yo [TOK*1024];
__device__ float g_Bp [TWO_D*TWO_D];
__device__ float g_Bw [KCONV*TWO_D];
__device__ float g_xm [TSTEPS*TWO_D];
__device__ float g_gate[TSTEPS*DDIM];
__device__ float g_src[TSTEPS*TWO_D];
__device__ float g_probs[TOK*4];
__device__ float2 g_hpA[256*256];
__device__ float2 g_hpB[256*256];

// ---------------- helpers ----------------
__device__ __forceinline__ float gelu_tanh(float x) {
    float x3 = x * x * x;
    return 0.5f * x * (1.0f + tanhf(0.7978845608028654f * (x + 0.044715f * x3)));
}

// ---------------- generic tiled SGEMM: C[M,N] = A[M,K] @ B[K,N] (+epilogue) ----
// Requires M%64==0, N%64==0, K%16==0.
// epilogue: v = acc; if bias v+=bias[n]; if add_src v+=add_src[m*N+n];
//           if act==2 v=gelu(v); if row_scale v*=row_scale[m*rs_stride];
//           C = beta? C+v : v
__global__ void sgemm_kernel(const float* __restrict__ A, const float* __restrict__ B,
                             float* __restrict__ C, int M, int N, int K,
                             const float* __restrict__ bias,
                             const float* __restrict__ add_src,
                             const float* __restrict__ row_scale, int rs_stride,
                             int beta, int act)
{
    const int BM = 64, BN = 64, BK = 16;
    __shared__ float As[16][64];
    __shared__ float Bs[16][64];

    int tid = threadIdx.x;            // 256 threads
    int bm = blockIdx.y * BM;
    int bn = blockIdx.x * BN;
    int tx = tid & 15, ty = tid >> 4; // 16x16 thread grid, 4x4 microtile each

    float acc[4][4];
    #pragma unroll
    for (int i = 0; i < 4; i++)
        #pragma unroll
        for (int j = 0; j < 4; j++) acc[i][j] = 0.0f;

    int arow = tid >> 2, acol4 = (tid & 3) * 4;   // A: 64 rows x 16 k (float4 along k)
    int brow = tid >> 4, bcol4 = (tid & 15) * 4;  // B: 16 rows x 64 n (float4 along n)

    const float* Aptr = A + (size_t)(bm + arow) * K + acol4;
    const float* Bptr = B + (size_t)brow * N + bn + bcol4;

    for (int k0 = 0; k0 < K; k0 += BK) {
        float4 av = *(const float4*)(Aptr + k0);
        float4 bv = *(const float4*)(Bptr + (size_t)k0 * N);
        As[acol4 + 0][arow] = av.x;
        As[acol4 + 1][arow] = av.y;
        As[acol4 + 2][arow] = av.z;
        As[acol4 + 3][arow] = av.w;
        *(float4*)&Bs[brow][bcol4] = bv;
        __syncthreads();

        #pragma unroll
        for (int k = 0; k < BK; k++) {
            float4 a = *(const float4*)&As[k][ty * 4];
            float4 b = *(const float4*)&Bs[k][tx * 4];
            float avr[4] = {a.x, a.y, a.z, a.w};
            float bvr[4] = {b.x, b.y, b.z, b.w};
            #pragma unroll
            for (int i = 0; i < 4; i++)
                #pragma unroll
                for (int j = 0; j < 4; j++) acc[i][j] += avr[i] * bvr[j];
        }
        __syncthreads();
    }

    #pragma unroll
    for (int i = 0; i < 4; i++) {
        int m = bm + ty * 4 + i;
        #pragma unroll
        for (int j = 0; j < 4; j++) {
            int n = bn + tx * 4 + j;
            float v = acc[i][j];
            if (bias)     v += bias[n];
            if (add_src)  v += add_src[(size_t)m * N + n];
            if (act == 2) v = gelu_tanh(v);
            if (row_scale) v *= row_scale[(size_t)m * rs_stride];
            size_t ci = (size_t)m * N + n;
            C[ci] = beta ? (C[ci] + v) : v;
        }
    }
}

// small matmul for M=8 rows: one thread per output element
// act: 0 none, 1 sigmoid
__global__ void small_mm(const float* __restrict__ A, const float* __restrict__ B,
                         float* __restrict__ C, int M, int N, int K,
                         const float* __restrict__ bias, int act)
{
    int n = blockIdx.x * blockDim.x + threadIdx.x;
    int m = blockIdx.y;
    if (n >= N || m >= M) return;
    float acc = 0.0f;
    for (int k = 0; k < K; k++) acc += A[m * K + k] * B[k * N + n];
    if (bias) acc += bias[n];
    if (act == 1) acc = 1.0f / (1.0f + expf(-acc));
    C[m * N + n] = acc;
}

// LayerNorm over 512 features, one block (256 threads) per token
__global__ void ln_kernel(const float* __restrict__ X, float* __restrict__ Y,
                          const float* __restrict__ w, const float* __restrict__ b)
{
    __shared__ float sh[256];
    int tok = blockIdx.x, tid = threadIdx.x;
    const float* x = X + (size_t)tok * 512;
    float v1 = x[tid], v2 = x[tid + 256];
    sh[tid] = v1 + v2;
    __syncthreads();
    for (int s = 128; s > 0; s >>= 1) { if (tid < s) sh[tid] += sh[tid + s]; __syncthreads(); }
    float mean = sh[0] * (1.0f / 512.0f);
    __syncthreads();
    float d1 = v1 - mean, d2 = v2 - mean;
    sh[tid] = d1 * d1 + d2 * d2;
    __syncthreads();
    for (int s = 128; s > 0; s >>= 1) { if (tid < s) sh[tid] += sh[tid + s]; __syncthreads(); }
    float rstd = rsqrtf(sh[0] * (1.0f / 512.0f) + 1e-5f);
    Y[(size_t)tok * 512 + tid]       = d1 * rstd * w[tid] + b[tid];
    Y[(size_t)tok * 512 + tid + 256] = d2 * rstd * w[tid + 256] + b[tid + 256];
}

// patchify: x (1,8,4,256,256) -> xp (2048, 1024) with k = c*256 + py*16 + px
__global__ void patchify_kernel(const float* __restrict__ x, float* __restrict__ xp)
{
    int idx = blockIdx.x * blockDim.x + threadIdx.x;
    if (idx >= TOK * 1024) return;
    int tok = idx >> 10, k = idx & 1023;
    int t = tok >> 8, hp = (tok >> 4) & 15, wp = tok & 15;
    int c = k >> 8, py = (k >> 4) & 15, px = k & 15;
    xp[idx] = x[(((size_t)(t * 4 + c) * 256) + hp * 16 + py) * 256 + wp * 16 + px];
}

// unpatchify: yo (2048, 1024) -> out (1,8,4,256,256)
__global__ void unpatchify_kernel(const float* __restrict__ yo, float* __restrict__ out)
{
    int idx = blockIdx.x * blockDim.x + threadIdx.x;
    if (idx >= TOK * 1024) return;
    int iw = idx & 255, ih = (idx >> 8) & 255, c = (idx >> 16) & 3, t = idx >> 18;
    int hp = ih >> 4, py = ih & 15, wp = iw >> 4, px = iw & 15;
    int tok = (t << 8) + hp * 16 + wp;
    out[idx] = yo[(size_t)tok * 1024 + c * 256 + py * 16 + px];
}

// pack complex matrix (Re,Im each 256x256, row-major in->out) into real 512x512
// [[Re, Im], [-Im, Re]]
__global__ void pack_cplx_kernel(const float* __restrict__ Re, const float* __restrict__ Im,
                                 float* __restrict__ Bp)
{
    int idx = blockIdx.x * blockDim.x + threadIdx.x;
    if (idx >= 512 * 512) return;
    int k = idx >> 9, n = idx & 511;
    float v;
    if (k < 256) v = (n < 256) ? Re[k * 256 + n] : Im[k * 256 + (n - 256)];
    else {
        int d = k - 256;
        v = (n < 256) ? -Im[d * 256 + n] : Re[d * 256 + (n - 256)];
    }
    Bp[idx] = v;
}

// pack conv weights (512,512,3,3) -> Bw[(ky*3+kx)*512+ic][oc]
__global__ void pack_conv_kernel(const float* __restrict__ cw, float* __restrict__ Bw)
{
    int idx = blockIdx.x * blockDim.x + threadIdx.x;
    if (idx >= KCONV * 512) return;
    int k = idx >> 9, oc = idx & 511;
    int pos = k / 512, ic = k - pos * 512;
    int ky = pos / 3, kx = pos - ky * 3;
    Bw[idx] = cw[(((size_t)oc * 512 + ic) * 3 + ky) * 3 + kx];
}

// im2col from token-major zn: col[tok][pos*512+ic], block per (tok,pos), 128 thr x float4
__global__ void im2col_kernel(const float* __restrict__ zn, float* __restrict__ col)
{
    int bid = blockIdx.x;
    int tok = bid / 9, pos = bid - tok * 9;
    int t = tok >> 8, hw = tok & 255;
    int y = hw >> 4, x = hw & 15;
    int ny = y + pos / 3 - 1, nx = x + pos % 3 - 1;
    float4* dst = (float4*)(col + (size_t)tok * KCONV + pos * 512);
    int i = threadIdx.x;  // 0..127
    if ((unsigned)ny < 16u && (unsigned)nx < 16u) {
        const float4* s = (const float4*)(zn + (size_t)(t * 256 + ny * 16 + nx) * 512);
        dst[i] = s[i];
    } else {
        dst[i] = make_float4(0.f, 0.f, 0.f, 0.f);
    }
}

// xm[t][c] = mean over 256 hw of xe[(t*256+hw)*512 + c]; grid 8 x 512 thr
__global__ void mean_kernel(const float* __restrict__ xe, float* __restrict__ xm)
{
    int t = blockIdx.x, c = threadIdx.x;
    float s = 0.0f;
    for (int hw = 0; hw < 256; hw++) s += xe[(size_t)((t << 8) + hw) * 512 + c];
    xm[t * 512 + c] = s * (1.0f / 256.0f);
}

// temporal recurrence per (hw, e); grid 256 blocks x 256 threads
__global__ void scan_kernel(const float* __restrict__ xe, const float* __restrict__ gate,
                            const float* __restrict__ src,
                            const float* __restrict__ lam_re, const float* __restrict__ lam_im,
                            const float* __restrict__ dt,
                            const float2* __restrict__ hprev,
                            float* __restrict__ hrow, float2* __restrict__ lasth)
{
    int e = threadIdx.x;
    int hw = blockIdx.x;
    float lr = lam_re[e], li = lam_im[e];
    float lamr = -(log1pf(expf(lr)) + 0.01f);
    float lami = li;
    float il2 = 1.0f / (lamr * lamr + lami * lami);
    float2 hp = hprev[hw * 256 + e];
    float hr = 0.0f, hi = 0.0f;
    float outr = 0.0f, outi = 0.0f;
    #pragma unroll
    for (int t = 0; t < TSTEPS; t++) {
        float d = dt[t];
        float ed = expf(lamr * d);
        float dr = ed * cosf(lami * d), di = ed * sinf(lami * d);
        float nr = dr - 1.0f;
        float ofr = (nr * lamr + di * lami) * il2;
        float ofi = (di * lamr - nr * lami) * il2;
        int tok = t * 256 + hw;
        float xr = xe[(size_t)tok * 512 + e], xi = xe[(size_t)tok * 512 + 256 + e];
        float g = gate[t * 256 + e];
        float sr = src[t * 512 + e], si = src[t * 512 + 256 + e];
        float fr = xr * g + sr * (1.0f - g);
        float fi = xi * g + si * (1.0f - g);
        float ur = fr * ofr - fi * ofi;
        float ui = fr * ofi + fi * ofr;
        float nhr = dr * hr - di * hi + ur;
        float nhi = dr * hi + di * hr + ui;
        hr = nhr; hi = nhi;
        outr = hr + (hp.x * dr - hp.y * di);
        outi = hi + (hp.x * di + hp.y * dr);
        hrow[(size_t)tok * 512 + e] = outr;
        hrow[(size_t)tok * 512 + 256 + e] = outi;
    }
    lasth[hw * 256 + e] = make_float2(outr, outi);
}

// router probs: warp per token, NE=4 logits + softmax
__global__ void probs_kernel(const float* __restrict__ xn, const float* __restrict__ Wr,
                             float* __restrict__ probs)
{
    int gwarp = (blockIdx.x * blockDim.x + threadIdx.x) >> 5;
    int lane = threadIdx.x & 31;
    if (gwarp >= TOK) return;
    const float* x = xn + (size_t)gwarp * 512;
    float l0 = 0, l1 = 0, l2 = 0, l3 = 0;
    for (int k = lane; k < 512; k += 32) {
        float xv = x[k];
        const float* wr = Wr + k * 4;
        l0 += xv * wr[0]; l1 += xv * wr[1]; l2 += xv * wr[2]; l3 += xv * wr[3];
    }
    #pragma unroll
    for (int off = 16; off > 0; off >>= 1) {
        l0 += __shfl_xor_sync(0xffffffffu, l0, off);
        l1 += __shfl_xor_sync(0xffffffffu, l1, off);
        l2 += __shfl_xor_sync(0xffffffffu, l2, off);
        l3 += __shfl_xor_sync(0xffffffffu, l3, off);
    }
    if (lane == 0) {
        float mx = fmaxf(fmaxf(l0, l1), fmaxf(l2, l3));
        float e0 = expf(l0 - mx), e1 = expf(l1 - mx), e2 = expf(l2 - mx), e3 = expf(l3 - mx);
        float inv = 1.0f / (e0 + e1 + e2 + e3);
        probs[gwarp * 4 + 0] = e0 * inv;
        probs[gwarp * 4 + 1] = e1 * inv;
        probs[gwarp * 4 + 2] = e2 * inv;
        probs[gwarp * 4 + 3] = e3 * inv;
    }
}

__global__ void add2_kernel(const float* __restrict__ a, const float* __restrict__ b,
                            float* __restrict__ c, int n)
{
    int i = blockIdx.x * blockDim.x + threadIdx.x;
    if (i < n) c[i] = a[i] + b[i];
}

__global__ void zero_f2_kernel(float2* p, int n)
{
    int i = blockIdx.x * blockDim.x + threadIdx.x;
    if (i < n) p[i] = make_float2(0.f, 0.f);
}

// ---------------- host orchestration ----------------
template <typename T>
static T* sym_addr(const T& sym) {
    void* p = nullptr;
    cudaGetSymbolAddress(&p, sym);
    return (T*)p;
}
template <typename T, size_t N>
static T* sym_addr(const T (&sym)[N]) {
    void* p = nullptr;
    cudaGetSymbolAddress(&p, sym);
    return (T*)p;
}

extern "C" void kernel_launch(void* const* d_in, const int* in_sizes, int n_in,
                              void* d_out, int out_size)
{
    const float* x      = (const float*)d_in[0];
    const float* dt     = (const float*)d_in[1];
    const float* Wenc   = (const float*)d_in[2];
    const float* benc   = (const float*)d_in[3];
    const float* Wdec   = (const float*)d_in[4];
    const float* bdec   = (const float*)d_in[5];
    const float* ln_sp_w= (const float*)d_in[6];
    const float* ln_sp_b= (const float*)d_in[7];
    const float* conv_w = (const float*)d_in[8];
    const float* conv_b = (const float*)d_in[9];
    const float* E_re   = (const float*)d_in[10];
    const float* E_im   = (const float*)d_in[11];
    const float* Ed_re  = (const float*)d_in[12];
    const float* Ed_im  = (const float*)d_in[13];
    const float* Ws_re  = (const float*)d_in[14];
    const float* Ws_im  = (const float*)d_in[15];
    const float* Wg     = (const float*)d_in[16];
    const float* bg     = (const float*)d_in[17];
    const float* lam_re = (const float*)d_in[18];
    const float* lam_im = (const float*)d_in[19];
    const float* ln_t_w = (const float*)d_in[20];
    const float* ln_t_b = (const float*)d_in[21];
    const float* Wr     = (const float*)d_in[22];
    const float* W1     = (const float*)d_in[23];
    const float* W2     = (const float*)d_in[24];

    float*  p_xp   = sym_addr(g_xp);
    float*  p_z    = sym_addr(g_z);
    float*  p_zn   = sym_addr(g_zn);
    float*  p_col  = sym_addr(g_col);
    float*  p_x    = sym_addr(g_x);
    float*  p_xe   = sym_addr(g_xe);
    float*  p_h    = sym_addr(g_h);
    float*  p_xo   = sym_addr(g_xo);
    float*  p_xn   = sym_addr(g_xn);
    float*  p_hid  = sym_addr(g_hid);
    float*  p_yo   = sym_addr(g_yo);
    float*  p_Bp   = sym_addr(g_Bp);
    float*  p_Bw   = sym_addr(g_Bw);
    float*  p_xm   = sym_addr(g_xm);
    float*  p_gate = sym_addr(g_gate);
    float*  p_src  = sym_addr(g_src);
    float*  p_probs= sym_addr(g_probs);
    float2* p_hpA  = sym_addr(g_hpA);
    float2* p_hpB  = sym_addr(g_hpB);

    // zero h_prev for layer 0
    zero_f2_kernel<<<256, 256>>>(p_hpA, 256 * 256);

    // encoder
    patchify_kernel<<<(TOK * 1024) / 256, 256>>>(x, p_xp);
    sgemm_kernel<<<dim3(512 / 64, TOK / 64), 256>>>(p_xp, Wenc, p_z, TOK, 512, 1024,
                                                    benc, nullptr, nullptr, 0, 0, 0);

    for (int l = 0; l < 2; l++) {
        const float* cE_re  = E_re  + l * 65536;
        const float* cE_im  = E_im  + l * 65536;
        const float* cEd_re = Ed_re + l * 65536;
        const float* cEd_im = Ed_im + l * 65536;
        const float* cWs_re = Ws_re + l * 65536;
        const float* cWs_im = Ws_im + l * 65536;

        // spatial LN
        ln_kernel<<<TOK, 256>>>(p_z, p_zn, ln_sp_w + l * 512, ln_sp_b + l * 512);

        // conv via im2col + GEMM, fused bias + residual (x = zf + conv)
        pack_conv_kernel<<<(KCONV * 512) / 256, 256>>>(conv_w + (size_t)l * 512 * 512 * 9, p_Bw);
        im2col_kernel<<<TOK * 9, 128>>>(p_zn, p_col);
        sgemm_kernel<<<dim3(512 / 64, TOK / 64), 256>>>(p_col, p_Bw, p_x, TOK, 512, KCONV,
                                                        conv_b + l * 512, p_z, nullptr, 0, 0, 0);

        // x_eigen = x @ E (complex via packed real GEMM)
        pack_cplx_kernel<<<1024, 256>>>(cE_re, cE_im, p_Bp);
        sgemm_kernel<<<dim3(512 / 64, TOK / 64), 256>>>(p_x, p_Bp, p_xe, TOK, 512, 512,
                                                        nullptr, nullptr, nullptr, 0, 0, 0);

        // spatial mean -> xm (8 x 512)
        mean_kernel<<<8, 512>>>(p_xe, p_xm);

        // source_seq = xm @ Ws (complex), gate_seq = sigmoid(xm @ Wg + bg)
        pack_cplx_kernel<<<1024, 256>>>(cWs_re, cWs_im, p_Bp);
        small_mm<<<dim3(4, 8), 128>>>(p_xm, p_Bp, p_src, 8, 512, 512, nullptr, 0);
        small_mm<<<dim3(2, 8), 128>>>(p_xm, Wg + l * 512 * 256, p_gate, 8, 256, 512,
                                      bg + l * 256, 1);

        // temporal scan -> h (token rows), last_h
        float2* hp_in  = (l == 0) ? p_hpA : p_hpB;
        float2* hp_out = (l == 0) ? p_hpB : p_hpA;
        scan_kernel<<<256, 256>>>(p_xe, p_gate, p_src, lam_re + l * 256, lam_im + l * 256,
                                  dt, hp_in, p_h, hp_out);

        // x_out = h @ Ed
        pack_cplx_kernel<<<1024, 256>>>(cEd_re, cEd_im, p_Bp);
        sgemm_kernel<<<dim3(512 / 64, TOK / 64), 256>>>(p_h, p_Bp, p_xo, TOK, 512, 512,
                                                        nullptr, nullptr, nullptr, 0, 0, 0);

        // temporal LN
        ln_kernel<<<TOK, 256>>>(p_xo, p_xn, ln_t_w + l * 512, ln_t_b + l * 512);

        // router probs
        probs_kernel<<<TOK / 8, 256>>>(p_xn, Wr + l * 512 * 4, p_probs);

        // z_next = x + xn  (then MoE experts accumulate into it)
        add2_kernel<<<(TOK * 512) / 256, 256>>>(p_x, p_xn, p_z, TOK * 512);

        // MoE: per expert, hid = gelu(xn @ W1[e]); z += probs[:,e] * (hid @ W2[e])
        for (int e = 0; e < 4; e++) {
            const float* w1 = W1 + ((size_t)l * 4 + e) * 512 * 1024;
            const float* w2 = W2 + ((size_t)l * 4 + e) * 1024 * 512;
            sgemm_kernel<<<dim3(1024 / 64, TOK / 64), 256>>>(p_xn, w1, p_hid, TOK, 1024, 512,
                                                             nullptr, nullptr, nullptr, 0, 0, 2);
            sgemm_kernel<<<dim3(512 / 64, TOK / 64), 256>>>(p_hid, w2, p_z, TOK, 512, 1024,
                                                            nullptr, nullptr, p_probs + e, 4, 1, 0);
        }
    }

    // decoder
    sgemm_kernel<<<dim3(1024 / 64, TOK / 64), 256>>>(p_z, Wdec, p_yo, TOK, 1024, 512,
                                                     bdec, nullptr, nullptr, 0, 0, 0);
    unpatchify_kernel<<<(TOK * 1024) / 256, 256>>>(p_yo, (float*)d_out);
}

// round 2
// speedup vs baseline: 1.3349x; 1.3349x over previous
#include <cuda_runtime.h>
#include <math.h>

// ---------------- problem constants ----------------
#define TOK   2048          // B*T*HP*WP
#define TWO_D 512
#define DDIM  256
#define KCONV 4608          // 512*9
#define TSTEPS 8

// epilogue flags
#define F_BIAS  1
#define F_ADD   2
#define F_GELU  4
#define F_SCALE 8

// ---------------- device scratch (no allocs allowed) ----------------
__device__ float g_xp  [TOK*1024];
__device__ float g_z   [TOK*TWO_D];
__device__ float g_zn  [TOK*TWO_D];
__device__ float g_col [TOK*KCONV];
__device__ float g_x   [TOK*TWO_D];
__device__ float g_xe  [TOK*TWO_D];
__device__ float g_h   [TOK*TWO_D];
__device__ float g_xo  [TOK*TWO_D];
__device__ float g_xn  [TOK*TWO_D];
__device__ float g_hid [4*TOK*1024];
__device__ float g_oexp[4*TOK*TWO_D];
__device__ float g_yo  [TOK*1024];
__device__ float g_Bp  [TWO_D*TWO_D];
__device__ float g_Bw  [KCONV*TWO_D];
__device__ float g_xm  [TSTEPS*TWO_D];
__device__ float g_gate[TSTEPS*DDIM];
__device__ float g_src [TSTEPS*TWO_D];
__device__ float g_probs[TOK*4];
__device__ float2 g_hpA[256*256];
__device__ float2 g_hpB[256*256];

// ---------------- helpers ----------------
__device__ __forceinline__ float gelu_tanh(float x) {
    float x3 = x * x * x;
    return 0.5f * x * (1.0f + tanhf(0.7978845608028654f * (x + 0.044715f * x3)));
}

// ---------------- SGEMM v2: 128x64 tile, BK=16, 256 thr, 8x4 microtile ------
// C[M,N] = A[M,K] @ B[K,N] (+ epilogue). M%128==0, N%64==0, K%16==0.
// Batched over blockIdx.z: A += z*strideA, B += z*strideB, C += z*strideC.
// epilogue: v=acc; +bias[n]; +add_src[m*N+n]; gelu; *probs[m*4+z]; store.
__global__ __launch_bounds__(256)
void sgemm2(const float* __restrict__ A, const float* __restrict__ B,
            float* __restrict__ C, int M, int N, int K,
            const float* __restrict__ bias,
            const float* __restrict__ add_src,
            const float* __restrict__ probs,
            int flags,
            long strideA, long strideB, long strideC)
{
    __shared__ float As[2][16][132];   // [buf][k][m], padded
    __shared__ float Bs[2][16][64];    // [buf][k][n]

    const int z = blockIdx.z;
    const float* Ap = A + (size_t)z * strideA;
    const float* Bp = B + (size_t)z * strideB;
    float*       Cp = C + (size_t)z * strideC;

    const int tid = threadIdx.x;
    const int bm = blockIdx.y * 128;
    const int bn = blockIdx.x * 64;
    const int tx = tid & 15;           // N dir: 16 * 4 = 64
    const int ty = tid >> 4;           // M dir: 16 * 8 = 128

    // global load mapping
    const int arow = tid >> 2;         // 0..63
    const int acol = (tid & 3) * 4;    // 0,4,8,12
    const int brow = tid >> 4;         // 0..15
    const int bcol = (tid & 15) * 4;   // 0..60

    const float* Ag = Ap + (size_t)(bm + arow) * K + acol;
    const float* Bg = Bp + (size_t)brow * N + bn + bcol;

    float acc[8][4];
    #pragma unroll
    for (int i = 0; i < 8; i++)
        #pragma unroll
        for (int j = 0; j < 4; j++) acc[i][j] = 0.0f;

    // preload tile 0 into buffer 0
    {
        float4 a0 = *(const float4*)(Ag);
        float4 a1 = *(const float4*)(Ag + (size_t)64 * K);
        float4 b0 = *(const float4*)(Bg);
        As[0][acol + 0][arow] = a0.x;
        As[0][acol + 1][arow] = a0.y;
        As[0][acol + 2][arow] = a0.z;
        As[0][acol + 3][arow] = a0.w;
        As[0][acol + 0][arow + 64] = a1.x;
        As[0][acol + 1][arow + 64] = a1.y;
        As[0][acol + 2][arow + 64] = a1.z;
        As[0][acol + 3][arow + 64] = a1.w;
        *(float4*)&Bs[0][brow][bcol] = b0;
    }
    __syncthreads();

    const int KT = K >> 4;
    for (int kt = 0; kt < KT; kt++) {
        const int cur = kt & 1, nxt = cur ^ 1;

        float4 na0, na1, nb0;
        const bool more = (kt + 1 < KT);
        if (more) {
            const float* Ag2 = Ag + (size_t)(kt + 1) * 16;
            na0 = *(const float4*)(Ag2);
            na1 = *(const float4*)(Ag2 + (size_t)64 * K);
            nb0 = *(const float4*)(Bg + (size_t)(kt + 1) * 16 * N);
        }

        #pragma unroll
        for (int k = 0; k < 16; k++) {
            float4 a0v = *(const float4*)(&As[cur][k][ty * 8]);
            float4 a1v = *(const float4*)(&As[cur][k][ty * 8 + 4]);
            float4 bv  = *(const float4*)(&Bs[cur][k][tx * 4]);
            float af[8] = {a0v.x, a0v.y, a0v.z, a0v.w, a1v.x, a1v.y, a1v.z, a1v.w};
            float bf[4] = {bv.x, bv.y, bv.z, bv.w};
            #pragma unroll
            for (int i = 0; i < 8; i++)
                #pragma unroll
                for (int j = 0; j < 4; j++)
                    acc[i][j] = fmaf(af[i], bf[j], acc[i][j]);
        }

        if (more) {
            As[nxt][acol + 0][arow] = na0.x;
            As[nxt][acol + 1][arow] = na0.y;
            As[nxt][acol + 2][arow] = na0.z;
            As[nxt][acol + 3][arow] = na0.w;
            As[nxt][acol + 0][arow + 64] = na1.x;
            As[nxt][acol + 1][arow + 64] = na1.y;
            As[nxt][acol + 2][arow + 64] = na1.z;
            As[nxt][acol + 3][arow + 64] = na1.w;
            *(float4*)&Bs[nxt][brow][bcol] = nb0;
            __syncthreads();
        }
    }

    // epilogue
    const int n0 = bn + tx * 4;
    #pragma unroll
    for (int i = 0; i < 8; i++) {
        const int m = bm + ty * 8 + i;
        float v0 = acc[i][0], v1 = acc[i][1], v2 = acc[i][2], v3 = acc[i][3];
        if (flags & F_BIAS) {
            const float4 bb = *(const float4*)&bias[n0];
            v0 += bb.x; v1 += bb.y; v2 += bb.z; v3 += bb.w;
        }
        if (flags & F_ADD) {
            const float4 r = *(const float4*)&add_src[(size_t)m * N + n0];
            v0 += r.x; v1 += r.y; v2 += r.z; v3 += r.w;
        }
        if (flags & F_GELU) {
            v0 = gelu_tanh(v0); v1 = gelu_tanh(v1);
            v2 = gelu_tanh(v2); v3 = gelu_tanh(v3);
        }
        if (flags & F_SCALE) {
            const float s = probs[(size_t)m * 4 + z];
            v0 *= s; v1 *= s; v2 *= s; v3 *= s;
        }
        float4 out; out.x = v0; out.y = v1; out.z = v2; out.w = v3;
        *(float4*)&Cp[(size_t)m * N + n0] = out;
    }
}

// small matmul for M=8 rows: one thread per output element. act 1 = sigmoid
__global__ void small_mm(const float* __restrict__ A, const float* __restrict__ B,
                         float* __restrict__ C, int M, int N, int K,
                         const float* __restrict__ bias, int act)
{
    int n = blockIdx.x * blockDim.x + threadIdx.x;
    int m = blockIdx.y;
    if (n >= N || m >= M) return;
    float acc = 0.0f;
    for (int k = 0; k < K; k++) acc += A[m * K + k] * B[k * N + n];
    if (bias) acc += bias[n];
    if (act == 1) acc = 1.0f / (1.0f + expf(-acc));
    C[m * N + n] = acc;
}

// LayerNorm over 512 features, one block (256 threads) per token
__global__ void ln_kernel(const float* __restrict__ X, float* __restrict__ Y,
                          const float* __restrict__ w, const float* __restrict__ b)
{
    __shared__ float sh[256];
    int tok = blockIdx.x, tid = threadIdx.x;
    const float* x = X + (size_t)tok * 512;
    float v1 = x[tid], v2 = x[tid + 256];
    sh[tid] = v1 + v2;
    __syncthreads();
    for (int s = 128; s > 0; s >>= 1) { if (tid < s) sh[tid] += sh[tid + s]; __syncthreads(); }
    float mean = sh[0] * (1.0f / 512.0f);
    __syncthreads();
    float d1 = v1 - mean, d2 = v2 - mean;
    sh[tid] = d1 * d1 + d2 * d2;
    __syncthreads();
    for (int s = 128; s > 0; s >>= 1) { if (tid < s) sh[tid] += sh[tid + s]; __syncthreads(); }
    float rstd = rsqrtf(sh[0] * (1.0f / 512.0f) + 1e-5f);
    Y[(size_t)tok * 512 + tid]       = d1 * rstd * w[tid] + b[tid];
    Y[(size_t)tok * 512 + tid + 256] = d2 * rstd * w[tid + 256] + b[tid + 256];
}

// patchify: x (1,8,4,256,256) -> xp (2048, 1024) with k = c*256 + py*16 + px
__global__ void patchify_kernel(const float* __restrict__ x, float* __restrict__ xp)
{
    int idx = blockIdx.x * blockDim.x + threadIdx.x;
    if (idx >= TOK * 1024) return;
    int tok = idx >> 10, k = idx & 1023;
    int t = tok >> 8, hp = (tok >> 4) & 15, wp = tok & 15;
    int c = k >> 8, py = (k >> 4) & 15, px = k & 15;
    xp[idx] = x[(((size_t)(t * 4 + c) * 256) + hp * 16 + py) * 256 + wp * 16 + px];
}

// unpatchify: yo (2048, 1024) -> out (1,8,4,256,256)
__global__ void unpatchify_kernel(const float* __restrict__ yo, float* __restrict__ out)
{
    int idx = blockIdx.x * blockDim.x + threadIdx.x;
    if (idx >= TOK * 1024) return;
    int iw = idx & 255, ih = (idx >> 8) & 255, c = (idx >> 16) & 3, t = idx >> 18;
    int hp = ih >> 4, py = ih & 15, wp = iw >> 4, px = iw & 15;
    int tok = (t << 8) + hp * 16 + wp;
    out[idx] = yo[(size_t)tok * 1024 + c * 256 + py * 16 + px];
}

// pack complex matrix into real 512x512 block matrix [[Re, Im], [-Im, Re]]
__global__ void pack_cplx_kernel(const float* __restrict__ Re, const float* __restrict__ Im,
                                 float* __restrict__ Bp)
{
    int idx = blockIdx.x * blockDim.x + threadIdx.x;
    if (idx >= 512 * 512) return;
    int k = idx >> 9, n = idx & 511;
    float v;
    if (k < 256) v = (n < 256) ? Re[k * 256 + n] : Im[k * 256 + (n - 256)];
    else {
        int d = k - 256;
        v = (n < 256) ? -Im[d * 256 + n] : Re[d * 256 + (n - 256)];
    }
    Bp[idx] = v;
}

// pack conv weights (512,512,3,3) -> Bw[(ky*3+kx)*512+ic][oc]
__global__ void pack_conv_kernel(const float* __restrict__ cw, float* __restrict__ Bw)
{
    int idx = blockIdx.x * blockDim.x + threadIdx.x;
    if (idx >= KCONV * 512) return;
    int k = idx >> 9, oc = idx & 511;
    int pos = k / 512, ic = k - pos * 512;
    int ky = pos / 3, kx = pos - ky * 3;
    Bw[idx] = cw[(((size_t)oc * 512 + ic) * 3 + ky) * 3 + kx];
}

// im2col from token-major zn: col[tok][pos*512+ic]
__global__ void im2col_kernel(const float* __restrict__ zn, float* __restrict__ col)
{
    int bid = blockIdx.x;
    int tok = bid / 9, pos = bid - tok * 9;
    int t = tok >> 8, hw = tok & 255;
    int y = hw >> 4, x = hw & 15;
    int ny = y + pos / 3 - 1, nx = x + pos % 3 - 1;
    float4* dst = (float4*)(col + (size_t)tok * KCONV + pos * 512);
    int i = threadIdx.x;  // 0..127
    if ((unsigned)ny < 16u && (unsigned)nx < 16u) {
        const float4* s = (const float4*)(zn + (size_t)(t * 256 + ny * 16 + nx) * 512);
        dst[i] = s[i];
    } else {
        dst[i] = make_float4(0.f, 0.f, 0.f, 0.f);
    }
}

// xm[t][c] = mean over 256 hw of xe[(t*256+hw)*512 + c]
__global__ void mean_kernel(const float* __restrict__ xe, float* __restrict__ xm)
{
    int t = blockIdx.x, c = threadIdx.x;
    float s = 0.0f;
    for (int hw = 0; hw < 256; hw++) s += xe[(size_t)((t << 8) + hw) * 512 + c];
    xm[t * 512 + c] = s * (1.0f / 256.0f);
}

// temporal recurrence per (hw, e)
__global__ void scan_kernel(const float* __restrict__ xe, const float* __restrict__ gate,
                            const float* __restrict__ src,
                            const float* __restrict__ lam_re, const float* __restrict__ lam_im,
                            const float* __restrict__ dt,
                            const float2* __restrict__ hprev,
                            float* __restrict__ hrow, float2* __restrict__ lasth)
{
    int e = threadIdx.x;
    int hw = blockIdx.x;
    float lr = lam_re[e], li = lam_im[e];
    float lamr = -(log1pf(expf(lr)) + 0.01f);
    float lami = li;
    float il2 = 1.0f / (lamr * lamr + lami * lami);
    float2 hp = hprev[hw * 256 + e];
    float hr = 0.0f, hi = 0.0f;
    float outr = 0.0f, outi = 0.0f;
    #pragma unroll
    for (int t = 0; t < TSTEPS; t++) {
        float d = dt[t];
        float ed = expf(lamr * d);
        float dr = ed * cosf(lami * d), di = ed * sinf(lami * d);
        float nr = dr - 1.0f;
        float ofr = (nr * lamr + di * lami) * il2;
        float ofi = (di * lamr - nr * lami) * il2;
        int tok = t * 256 + hw;
        float xr = xe[(size_t)tok * 512 + e], xi = xe[(size_t)tok * 512 + 256 + e];
        float g = gate[t * 256 + e];
        float sr = src[t * 512 + e], si = src[t * 512 + 256 + e];
        float fr = xr * g + sr * (1.0f - g);
        float fi = xi * g + si * (1.0f - g);
        float ur = fr * ofr - fi * ofi;
        float ui = fr * ofi + fi * ofr;
        float nhr = dr * hr - di * hi + ur;
        float nhi = dr * hi + di * hr + ui;
        hr = nhr; hi = nhi;
        outr = hr + (hp.x * dr - hp.y * di);
        outi = hi + (hp.x * di + hp.y * dr);
        hrow[(size_t)tok * 512 + e] = outr;
        hrow[(size_t)tok * 512 + 256 + e] = outi;
    }
    lasth[hw * 256 + e] = make_float2(outr, outi);
}

// router probs: warp per token, NE=4 logits + softmax
__global__ void probs_kernel(const float* __restrict__ xn, const float* __restrict__ Wr,
                             float* __restrict__ probs)
{
    int gwarp = (blockIdx.x * blockDim.x + threadIdx.x) >> 5;
    int lane = threadIdx.x & 31;
    if (gwarp >= TOK) return;
    const float* x = xn + (size_t)gwarp * 512;
    float l0 = 0, l1 = 0, l2 = 0, l3 = 0;
    for (int k = lane; k < 512; k += 32) {
        float xv = x[k];
        const float* wr = Wr + k * 4;
        l0 += xv * wr[0]; l1 += xv * wr[1]; l2 += xv * wr[2]; l3 += xv * wr[3];
    }
    #pragma unroll
    for (int off = 16; off > 0; off >>= 1) {
        l0 += __shfl_xor_sync(0xffffffffu, l0, off);
        l1 += __shfl_xor_sync(0xffffffffu, l1, off);
        l2 += __shfl_xor_sync(0xffffffffu, l2, off);
        l3 += __shfl_xor_sync(0xffffffffu, l3, off);
    }
    if (lane == 0) {
        float mx = fmaxf(fmaxf(l0, l1), fmaxf(l2, l3));
        float e0 = expf(l0 - mx), e1 = expf(l1 - mx), e2 = expf(l2 - mx), e3 = expf(l3 - mx);
        float inv = 1.0f / (e0 + e1 + e2 + e3);
        probs[gwarp * 4 + 0] = e0 * inv;
        probs[gwarp * 4 + 1] = e1 * inv;
        probs[gwarp * 4 + 2] = e2 * inv;
        probs[gwarp * 4 + 3] = e3 * inv;
    }
}

// z = x + xn + sum_e oexp[e]   (float4 over TOK*512)
__global__ void reduce_moe_kernel(const float* __restrict__ x, const float* __restrict__ xn,
                                  const float* __restrict__ oexp, float* __restrict__ z)
{
    int i = blockIdx.x * blockDim.x + threadIdx.x;
    const int n4 = TOK * TWO_D / 4;
    if (i >= n4) return;
    const float4* x4  = (const float4*)x;
    const float4* xn4 = (const float4*)xn;
    const float4* o4  = (const float4*)oexp;
    float4 a = x4[i], b = xn4[i];
    float4 o0 = o4[i], o1 = o4[i + n4], o2 = o4[i + 2 * n4], o3 = o4[i + 3 * n4];
    float4 r;
    r.x = a.x + b.x + o0.x + o1.x + o2.x + o3.x;
    r.y = a.y + b.y + o0.y + o1.y + o2.y + o3.y;
    r.z = a.z + b.z + o0.z + o1.z + o2.z + o3.z;
    r.w = a.w + b.w + o0.w + o1.w + o2.w + o3.w;
    ((float4*)z)[i] = r;
}

__global__ void zero_f2_kernel(float2* p, int n)
{
    int i = blockIdx.x * blockDim.x + threadIdx.x;
    if (i < n) p[i] = make_float2(0.f, 0.f);
}

// ---------------- host orchestration ----------------
template <typename T>
static T* sym_addr(const T& sym) {
    void* p = nullptr;
    cudaGetSymbolAddress(&p, (const void*)&sym);
    return (T*)p;
}
template <typename T, size_t N>
static T* sym_addr(const T (&sym)[N]) {
    void* p = nullptr;
    cudaGetSymbolAddress(&p, (const void*)&sym);
    return (T*)p;
}

extern "C" void kernel_launch(void* const* d_in, const int* in_sizes, int n_in,
                              void* d_out, int out_size)
{
    const float* x      = (const float*)d_in[0];
    const float* dt     = (const float*)d_in[1];
    const float* Wenc   = (const float*)d_in[2];
    const float* benc   = (const float*)d_in[3];
    const float* Wdec   = (const float*)d_in[4];
    const float* bdec   = (const float*)d_in[5];
    const float* ln_sp_w= (const float*)d_in[6];
    const float* ln_sp_b= (const float*)d_in[7];
    const float* conv_w = (const float*)d_in[8];
    const float* conv_b = (const float*)d_in[9];
    const float* E_re   = (const float*)d_in[10];
    const float* E_im   = (const float*)d_in[11];
    const float* Ed_re  = (const float*)d_in[12];
    const float* Ed_im  = (const float*)d_in[13];
    const float* Ws_re  = (const float*)d_in[14];
    const float* Ws_im  = (const float*)d_in[15];
    const float* Wg     = (const float*)d_in[16];
    const float* bg     = (const float*)d_in[17];
    const float* lam_re = (const float*)d_in[18];
    const float* lam_im = (const float*)d_in[19];
    const float* ln_t_w = (const float*)d_in[20];
    const float* ln_t_b = (const float*)d_in[21];
    const float* Wr     = (const float*)d_in[22];
    const float* W1     = (const float*)d_in[23];
    const float* W2     = (const float*)d_in[24];

    float*  p_xp   = sym_addr(g_xp);
    float*  p_z    = sym_addr(g_z);
    float*  p_zn   = sym_addr(g_zn);
    float*  p_col  = sym_addr(g_col);
    float*  p_x    = sym_addr(g_x);
    float*  p_xe   = sym_addr(g_xe);
    float*  p_h    = sym_addr(g_h);
    float*  p_xo   = sym_addr(g_xo);
    float*  p_xn   = sym_addr(g_xn);
    float*  p_hid  = sym_addr(g_hid);
    float*  p_oexp = sym_addr(g_oexp);
    float*  p_yo   = sym_addr(g_yo);
    float*  p_Bp   = sym_addr(g_Bp);
    float*  p_Bw   = sym_addr(g_Bw);
    float*  p_xm   = sym_addr(g_xm);
    float*  p_gate = sym_addr(g_gate);
    float*  p_src  = sym_addr(g_src);
    float*  p_probs= sym_addr(g_probs);
    float2* p_hpA  = sym_addr(g_hpA);
    float2* p_hpB  = sym_addr(g_hpB);

    // zero h_prev for layer 0
    zero_f2_kernel<<<256, 256>>>(p_hpA, 256 * 256);

    // encoder
    patchify_kernel<<<(TOK * 1024) / 256, 256>>>(x, p_xp);
    sgemm2<<<dim3(512 / 64, TOK / 128, 1), 256>>>(p_xp, Wenc, p_z, TOK, 512, 1024,
                                                  benc, nullptr, nullptr, F_BIAS, 0, 0, 0);

    for (int l = 0; l < 2; l++) {
        const float* cE_re  = E_re  + l * 65536;
        const float* cE_im  = E_im  + l * 65536;
        const float* cEd_re = Ed_re + l * 65536;
        const float* cEd_im = Ed_im + l * 65536;
        const float* cWs_re = Ws_re + l * 65536;
        const float* cWs_im = Ws_im + l * 65536;

        // spatial LN
        ln_kernel<<<TOK, 256>>>(p_z, p_zn, ln_sp_w + l * 512, ln_sp_b + l * 512);

        // conv via im2col + GEMM, fused bias + residual (x = zf + conv)
        pack_conv_kernel<<<(KCONV * 512) / 256, 256>>>(conv_w + (size_t)l * 512 * 512 * 9, p_Bw);
        im2col_kernel<<<TOK * 9, 128>>>(p_zn, p_col);
        sgemm2<<<dim3(512 / 64, TOK / 128, 1), 256>>>(p_col, p_Bw, p_x, TOK, 512, KCONV,
                                                      conv_b + l * 512, p_z, nullptr,
                                                      F_BIAS | F_ADD, 0, 0, 0);

        // x_eigen = x @ E (complex via packed real GEMM)
        pack_cplx_kernel<<<1024, 256>>>(cE_re, cE_im, p_Bp);
        sgemm2<<<dim3(512 / 64, TOK / 128, 1), 256>>>(p_x, p_Bp, p_xe, TOK, 512, 512,
                                                      nullptr, nullptr, nullptr, 0, 0, 0, 0);

        // spatial mean -> xm (8 x 512)
        mean_kernel<<<8, 512>>>(p_xe, p_xm);

        // source_seq = xm @ Ws (complex), gate_seq = sigmoid(xm @ Wg + bg)
        pack_cplx_kernel<<<1024, 256>>>(cWs_re, cWs_im, p_Bp);
        small_mm<<<dim3(4, 8), 128>>>(p_xm, p_Bp, p_src, 8, 512, 512, nullptr, 0);
        small_mm<<<dim3(2, 8), 128>>>(p_xm, Wg + l * 512 * 256, p_gate, 8, 256, 512,
                                      bg + l * 256, 1);

        // temporal scan -> h (token rows), last_h
        float2* hp_in  = (l == 0) ? p_hpA : p_hpB;
        float2* hp_out = (l == 0) ? p_hpB : p_hpA;
        scan_kernel<<<256, 256>>>(p_xe, p_gate, p_src, lam_re + l * 256, lam_im + l * 256,
                                  dt, hp_in, p_h, hp_out);

        // x_out = h @ Ed
        pack_cplx_kernel<<<1024, 256>>>(cEd_re, cEd_im, p_Bp);
        sgemm2<<<dim3(512 / 64, TOK / 128, 1), 256>>>(p_h, p_Bp, p_xo, TOK, 512, 512,
                                                      nullptr, nullptr, nullptr, 0, 0, 0, 0);

        // temporal LN
        ln_kernel<<<TOK, 256>>>(p_xo, p_xn, ln_t_w + l * 512, ln_t_b + l * 512);

        // router probs
        probs_kernel<<<TOK / 8, 256>>>(p_xn, Wr + l * 512 * 4, p_probs);

        // MoE batched: hid[e] = gelu(xn @ W1[e]) for all 4 experts in one launch
        sgemm2<<<dim3(1024 / 64, TOK / 128, 4), 256>>>(
            p_xn, W1 + (size_t)l * 4 * 512 * 1024, p_hid, TOK, 1024, 512,
            nullptr, nullptr, nullptr, F_GELU,
            0, (long)512 * 1024, (long)TOK * 1024);

        // oexp[e] = probs[:,e] * (hid[e] @ W2[e])
        sgemm2<<<dim3(512 / 64, TOK / 128, 4), 256>>>(
            p_hid, W2 + (size_t)l * 4 * 1024 * 512, p_oexp, TOK, 512, 1024,
            nullptr, nullptr, p_probs, F_SCALE,
            (long)TOK * 1024, (long)1024 * 512, (long)TOK * 512);

        // z_next = x + xn + sum_e oexp[e]
        reduce_moe_kernel<<<(TOK * 512 / 4 + 255) / 256, 256>>>(p_x, p_xn, p_oexp, p_z);
    }

    // decoder
    sgemm2<<<dim3(1024 / 64, TOK / 128, 1), 256>>>(p_z, Wdec, p_yo, TOK, 1024, 512,
                                                   bdec, nullptr, nullptr, F_BIAS, 0, 0, 0);
    unpatchify_kernel<<<(TOK * 1024) / 256, 256>>>(p_yo, (float*)d_out);
}

// round 4
// speedup vs baseline: 1.8065x; 1.3533x over previous
#include <cuda_runtime.h>
#include <cuda_bf16.h>
#include <math.h>
#include <stdint.h>

// ---------------- problem constants ----------------
#define TOK   2048          // B*T*HP*WP
#define TWO_D 512
#define DDIM  256
#define KCONV 4608          // 512*9
#define TSTEPS 8
#define PADK  72            // 64 + 8 bf16 row padding

// epilogue flags
#define F_BIAS  1
#define F_ADD   2
#define F_GELU  4
#define F_SCALE 8

// ---------------- device scratch (no allocs allowed) ----------------
__device__ float g_xp  [TOK*1024];
__device__ float g_z   [TOK*TWO_D];
__device__ float g_zn  [TOK*TWO_D];
__device__ float g_col [TOK*KCONV];
__device__ float g_x   [TOK*TWO_D];
__device__ float g_xe  [TOK*TWO_D];
__device__ float g_h   [TOK*TWO_D];
__device__ float g_xo  [TOK*TWO_D];
__device__ float g_xn  [TOK*TWO_D];
__device__ float g_hid [4*TOK*1024];
__device__ float g_oexp[4*TOK*TWO_D];
__device__ float g_yo  [TOK*1024];
__device__ float g_Bp  [TWO_D*TWO_D];
__device__ float g_xm  [TSTEPS*TWO_D];
__device__ float g_gate[TSTEPS*DDIM];
__device__ float g_src [TSTEPS*TWO_D];
__device__ float g_probs[TOK*4];
__device__ float2 g_hpA[256*256];
__device__ float2 g_hpB[256*256];

// bf16 hi/lo operand buffers
__device__ __nv_bfloat16 g_Ahi[TOK*KCONV];   // max A: col 2048x4608
__device__ __nv_bfloat16 g_Alo[TOK*KCONV];
__device__ __nv_bfloat16 g_Bhi[512*KCONV];   // max B: conv weights 512x4608 (N-major)
__device__ __nv_bfloat16 g_Blo[512*KCONV];

// ---------------- helpers ----------------
__device__ __forceinline__ uint32_t smem_to_u32(const void* smem_ptr) {
    uint32_t addr;
    asm("{ .reg .u64 tmp; cvta.to.shared.u64 tmp, %1; cvt.u32.u64 %0, tmp; }"
        : "=r"(addr) : "l"(smem_ptr));
    return addr;
}
__device__ __forceinline__ float gelu_tanh(float x) {
    float x3 = x * x * x;
    return 0.5f * x * (1.0f + tanhf(0.7978845608028654f * (x + 0.044715f * x3)));
}
__device__ __forceinline__ void ldsm_x4(uint32_t* r, uint32_t addr) {
    asm volatile("ldmatrix.sync.aligned.m8n8.x4.shared.b16 {%0,%1,%2,%3}, [%4];"
        : "=r"(r[0]), "=r"(r[1]), "=r"(r[2]), "=r"(r[3]) : "r"(addr));
}
__device__ __forceinline__ void ldsm_x2(uint32_t* r, uint32_t addr) {
    asm volatile("ldmatrix.sync.aligned.m8n8.x2.shared.b16 {%0,%1}, [%2];"
        : "=r"(r[0]), "=r"(r[1]) : "r"(addr));
}
__device__ __forceinline__ void mma_bf16(float* d, const uint32_t* a, const uint32_t* b) {
    asm volatile(
        "mma.sync.aligned.m16n8k16.row.col.f32.bf16.bf16.f32 "
        "{%0,%1,%2,%3}, {%4,%5,%6,%7}, {%8,%9}, {%0,%1,%2,%3};"
        : "+f"(d[0]), "+f"(d[1]), "+f"(d[2]), "+f"(d[3])
        : "r"(a[0]), "r"(a[1]), "r"(a[2]), "r"(a[3]), "r"(b[0]), "r"(b[1]));
}

// ================= tensor-core GEMM (bf16x3 split, mma.sync) =================
// C[M,N] = fp32(A) @ fp32(B); A ≈ Ahi+Alo row-major [M][K]; B N-major [N][K].
// CTA tile 128x128, K-tile 64, 8 warps, warp tile 64x32.
// M%128==0, N%128==0, K%64==0. Batched over blockIdx.z (strides in elements).
__global__ __launch_bounds__(256, 2)
void tgemm(const __nv_bfloat16* __restrict__ Ahi, const __nv_bfloat16* __restrict__ Alo,
           const __nv_bfloat16* __restrict__ Bhi, const __nv_bfloat16* __restrict__ Blo,
           float* __restrict__ C, int M, int N, int K,
           const float* __restrict__ bias,
           const float* __restrict__ add_src,
           const float* __restrict__ probs,
           int flags, long sA, long sB, long sC)
{
    extern __shared__ __nv_bfloat16 sm[];
    __nv_bfloat16* sAh = sm;
    __nv_bfloat16* sAl = sm + 128 * PADK;
    __nv_bfloat16* sBh = sm + 2 * 128 * PADK;
    __nv_bfloat16* sBl = sm + 3 * 128 * PADK;
    const uint32_t uAh = smem_to_u32(sAh);
    const uint32_t uAl = smem_to_u32(sAl);
    const uint32_t uBh = smem_to_u32(sBh);
    const uint32_t uBl = smem_to_u32(sBl);

    const int tid = threadIdx.x;
    const int wid = tid >> 5;
    const int lane = tid & 31;
    const int warp_m = wid >> 2;       // 0..1 -> 64 rows each
    const int warp_n = wid & 3;        // 0..3 -> 32 cols each

    const int z = blockIdx.z;
    const __nv_bfloat16* Ah = Ahi + (size_t)z * sA;
    const __nv_bfloat16* Al = Alo + (size_t)z * sA;
    const __nv_bfloat16* Bh = Bhi + (size_t)z * sB;
    const __nv_bfloat16* Bl = Blo + (size_t)z * sB;
    float* Cp = C + (size_t)z * sC;
    const int bm = blockIdx.y * 128;
    const int bn = blockIdx.x * 128;

    float acc[4][4][4];
    #pragma unroll
    for (int i = 0; i < 4; i++)
        #pragma unroll
        for (int j = 0; j < 4; j++)
            #pragma unroll
            for (int q = 0; q < 4; q++) acc[i][j][q] = 0.0f;

    // global load mapping: 256 threads, each uint4 (8 bf16); 4 iters cover 128x64
    const int grow = tid >> 3;         // 0..31 (+32 per iter)
    const int gkc  = (tid & 7) * 8;    // 0..56

    // smem addresses for ldmatrix (A: 16x16 via x4, B: 8x16 via x2)
    const uint32_t aoff = (uint32_t)((warp_m * 64 + (lane & 15)) * PADK + (lane >> 4) * 8) * 2;
    const uint32_t boff = (uint32_t)((warp_n * 32 + (lane & 7)) * PADK + ((lane >> 3) & 1) * 8) * 2;

    const int KT = K >> 6;
    for (int kt = 0; kt < KT; kt++) {
        const int k0 = kt << 6;
        #pragma unroll
        for (int it = 0; it < 4; it++) {
            const int row = grow + it * 32;
            const int so = row * PADK + gkc;
            const size_t ga = (size_t)(bm + row) * K + k0 + gkc;
            const size_t gb = (size_t)(bn + row) * K + k0 + gkc;
            *(uint4*)(sAh + so) = *(const uint4*)(Ah + ga);
            *(uint4*)(sAl + so) = *(const uint4*)(Al + ga);
            *(uint4*)(sBh + so) = *(const uint4*)(Bh + gb);
            *(uint4*)(sBl + so) = *(const uint4*)(Bl + gb);
        }
        __syncthreads();

        #pragma unroll
        for (int ks = 0; ks < 4; ks++) {
            const uint32_t kb = (uint32_t)(ks * 16) * 2;
            uint32_t ah[4][4], al[4][4];
            #pragma unroll
            for (int mi = 0; mi < 4; mi++) {
                const uint32_t ao = aoff + (uint32_t)(mi * 16 * PADK) * 2 + kb;
                ldsm_x4(ah[mi], uAh + ao);
                ldsm_x4(al[mi], uAl + ao);
            }
            #pragma unroll
            for (int nj = 0; nj < 4; nj++) {
                const uint32_t bo = boff + (uint32_t)(nj * 8 * PADK) * 2 + kb;
                uint32_t bh[2], bl[2];
                ldsm_x2(bh, uBh + bo);
                ldsm_x2(bl, uBl + bo);
                #pragma unroll
                for (int mi = 0; mi < 4; mi++) {
                    mma_bf16(acc[mi][nj], ah[mi], bh);
                    mma_bf16(acc[mi][nj], ah[mi], bl);
                    mma_bf16(acc[mi][nj], al[mi], bh);
                }
            }
        }
        __syncthreads();
    }

    // epilogue: frag (m16n8): d0,d1 -> (r, c..c+1); d2,d3 -> (r+8, c..c+1)
    #pragma unroll
    for (int mi = 0; mi < 4; mi++) {
        #pragma unroll
        for (int nj = 0; nj < 4; nj++) {
            const int m0 = bm + warp_m * 64 + mi * 16 + (lane >> 2);
            const int n0 = bn + warp_n * 32 + nj * 8 + (lane & 3) * 2;
            float v00 = acc[mi][nj][0], v01 = acc[mi][nj][1];
            float v10 = acc[mi][nj][2], v11 = acc[mi][nj][3];
            if (flags & F_BIAS) {
                const float2 bb = *(const float2*)&bias[n0];
                v00 += bb.x; v01 += bb.y; v10 += bb.x; v11 += bb.y;
            }
            if (flags & F_ADD) {
                const float2 r0 = *(const float2*)&add_src[(size_t)m0 * N + n0];
                const float2 r1 = *(const float2*)&add_src[(size_t)(m0 + 8) * N + n0];
                v00 += r0.x; v01 += r0.y; v10 += r1.x; v11 += r1.y;
            }
            if (flags & F_GELU) {
                v00 = gelu_tanh(v00); v01 = gelu_tanh(v01);
                v10 = gelu_tanh(v10); v11 = gelu_tanh(v11);
            }
            if (flags & F_SCALE) {
                const float s0 = probs[(size_t)m0 * 4 + z];
                const float s1 = probs[(size_t)(m0 + 8) * 4 + z];
                v00 *= s0; v01 *= s0; v10 *= s1; v11 *= s1;
            }
            float2 o0; o0.x = v00; o0.y = v01;
            float2 o1; o1.x = v10; o1.y = v11;
            *(float2*)&Cp[(size_t)m0 * N + n0] = o0;
            *(float2*)&Cp[(size_t)(m0 + 8) * N + n0] = o1;
        }
    }
}

// ================= fp32 -> bf16 hi/lo split (elementwise) =================
__global__ void split_kernel(const float4* __restrict__ src,
                             __nv_bfloat162* __restrict__ hi,
                             __nv_bfloat162* __restrict__ lo, int n4)
{
    int i = blockIdx.x * blockDim.x + threadIdx.x;
    if (i >= n4) return;
    float4 v = src[i];
    __nv_bfloat16 h0 = __float2bfloat16(v.x);
    __nv_bfloat16 h1 = __float2bfloat16(v.y);
    __nv_bfloat16 h2 = __float2bfloat16(v.z);
    __nv_bfloat16 h3 = __float2bfloat16(v.w);
    __nv_bfloat16 l0 = __float2bfloat16(v.x - __bfloat162float(h0));
    __nv_bfloat16 l1 = __float2bfloat16(v.y - __bfloat162float(h1));
    __nv_bfloat16 l2 = __float2bfloat16(v.z - __bfloat162float(h2));
    __nv_bfloat16 l3 = __float2bfloat16(v.w - __bfloat162float(h3));
    hi[2 * i]     = __halves2bfloat162(h0, h1);
    hi[2 * i + 1] = __halves2bfloat162(h2, h3);
    lo[2 * i]     = __halves2bfloat162(l0, l1);
    lo[2 * i + 1] = __halves2bfloat162(l2, l3);
}

// transpose + split: out[z][n*K+k] = src[z*sSrc + k*N + n]
__global__ void tsplit_kernel(const float* __restrict__ src,
                              __nv_bfloat16* __restrict__ hi,
                              __nv_bfloat16* __restrict__ lo,
                              int K, int N, long sSrc, long sDst)
{
    long idx = (long)blockIdx.x * blockDim.x + threadIdx.x;
    long total = (long)K * N;
    if (idx >= total) return;
    int z = blockIdx.y;
    int n = (int)(idx / K);
    int k = (int)(idx - (long)n * K);
    float v = src[(size_t)z * sSrc + (size_t)k * N + n];
    __nv_bfloat16 h = __float2bfloat16(v);
    hi[(size_t)z * sDst + idx] = h;
    lo[(size_t)z * sDst + idx] = __float2bfloat16(v - __bfloat162float(h));
}

// pack complex (Re,Im 256x256) -> Bt[n][k] of the 512x512 block matrix, split
__global__ void pack_cplx_bt(const float* __restrict__ Re, const float* __restrict__ Im,
                             __nv_bfloat16* __restrict__ hi, __nv_bfloat16* __restrict__ lo)
{
    int idx = blockIdx.x * blockDim.x + threadIdx.x;
    if (idx >= 512 * 512) return;
    int n = idx >> 9, k = idx & 511;
    float v;
    if (k < 256) v = (n < 256) ? Re[k * 256 + n] : Im[k * 256 + (n - 256)];
    else {
        int d = k - 256;
        v = (n < 256) ? -Im[d * 256 + n] : Re[d * 256 + (n - 256)];
    }
    __nv_bfloat16 h = __float2bfloat16(v);
    hi[idx] = h;
    lo[idx] = __float2bfloat16(v - __bfloat162float(h));
}

// conv weights (512,512,3,3) -> Bt[oc][pos*512+ic], split
__global__ void conv_w_tsplit(const float* __restrict__ cw,
                              __nv_bfloat16* __restrict__ hi, __nv_bfloat16* __restrict__ lo)
{
    int idx = blockIdx.x * blockDim.x + threadIdx.x;
    if (idx >= 512 * KCONV) return;
    int oc = idx / KCONV, kk = idx - oc * KCONV;
    int ic = kk & 511, pos = kk >> 9;
    int ky = pos / 3, kx = pos - ky * 3;
    float v = cw[(((size_t)oc * 512 + ic) * 3 + ky) * 3 + kx];
    __nv_bfloat16 h = __float2bfloat16(v);
    hi[idx] = h;
    lo[idx] = __float2bfloat16(v - __bfloat162float(h));
}

// ================= elementwise / small kernels =================
__global__ void small_mm(const float* __restrict__ A, const float* __restrict__ B,
                         float* __restrict__ C, int M, int N, int K,
                         const float* __restrict__ bias, int act)
{
    int n = blockIdx.x * blockDim.x + threadIdx.x;
    int m = blockIdx.y;
    if (n >= N || m >= M) return;
    float acc = 0.0f;
    for (int k = 0; k < K; k++) acc += A[m * K + k] * B[k * N + n];
    if (bias) acc += bias[n];
    if (act == 1) acc = 1.0f / (1.0f + expf(-acc));
    C[m * N + n] = acc;
}

__global__ void ln_kernel(const float* __restrict__ X, float* __restrict__ Y,
                          const float* __restrict__ w, const float* __restrict__ b)
{
    __shared__ float sh[256];
    int tok = blockIdx.x, tid = threadIdx.x;
    const float* x = X + (size_t)tok * 512;
    float v1 = x[tid], v2 = x[tid + 256];
    sh[tid] = v1 + v2;
    __syncthreads();
    for (int s = 128; s > 0; s >>= 1) { if (tid < s) sh[tid] += sh[tid + s]; __syncthreads(); }
    float mean = sh[0] * (1.0f / 512.0f);
    __syncthreads();
    float d1 = v1 - mean, d2 = v2 - mean;
    sh[tid] = d1 * d1 + d2 * d2;
    __syncthreads();
    for (int s = 128; s > 0; s >>= 1) { if (tid < s) sh[tid] += sh[tid + s]; __syncthreads(); }
    float rstd = rsqrtf(sh[0] * (1.0f / 512.0f) + 1e-5f);
    Y[(size_t)tok * 512 + tid]       = d1 * rstd * w[tid] + b[tid];
    Y[(size_t)tok * 512 + tid + 256] = d2 * rstd * w[tid + 256] + b[tid + 256];
}

__global__ void patchify_kernel(const float* __restrict__ x, float* __restrict__ xp)
{
    int idx = blockIdx.x * blockDim.x + threadIdx.x;
    if (idx >= TOK * 1024) return;
    int tok = idx >> 10, k = idx & 1023;
    int t = tok >> 8, hp = (tok >> 4) & 15, wp = tok & 15;
    int c = k >> 8, py = (k >> 4) & 15, px = k & 15;
    xp[idx] = x[(((size_t)(t * 4 + c) * 256) + hp * 16 + py) * 256 + wp * 16 + px];
}

__global__ void unpatchify_kernel(const float* __restrict__ yo, float* __restrict__ out)
{
    int idx = blockIdx.x * blockDim.x + threadIdx.x;
    if (idx >= TOK * 1024) return;
    int iw = idx & 255, ih = (idx >> 8) & 255, c = (idx >> 16) & 3, t = idx >> 18;
    int hp = ih >> 4, py = ih & 15, wp = iw >> 4, px = iw & 15;
    int tok = (t << 8) + hp * 16 + wp;
    out[idx] = yo[(size_t)tok * 1024 + c * 256 + py * 16 + px];
}

// fp32 pack (only for the tiny small_mm path, Ws)
__global__ void pack_cplx_kernel(const float* __restrict__ Re, const float* __restrict__ Im,
                                 float* __restrict__ Bp)
{
    int idx = blockIdx.x * blockDim.x + threadIdx.x;
    if (idx >= 512 * 512) return;
    int k = idx >> 9, n = idx & 511;
    float v;
    if (k < 256) v = (n < 256) ? Re[k * 256 + n] : Im[k * 256 + (n - 256)];
    else {
        int d = k - 256;
        v = (n < 256) ? -Im[d * 256 + n] : Re[d * 256 + (n - 256)];
    }
    Bp[idx] = v;
}

__global__ void im2col_kernel(const float* __restrict__ zn, float* __restrict__ col)
{
    int bid = blockIdx.x;
    int tok = bid / 9, pos = bid - tok * 9;
    int t = tok >> 8, hw = tok & 255;
    int y = hw >> 4, x = hw & 15;
    int ny = y + pos / 3 - 1, nx = x + pos % 3 - 1;
    float4* dst = (float4*)(col + (size_t)tok * KCONV + pos * 512);
    int i = threadIdx.x;  // 0..127
    if ((unsigned)ny < 16u && (unsigned)nx < 16u) {
        const float4* s = (const float4*)(zn + (size_t)(t * 256 + ny * 16 + nx) * 512);
        dst[i] = s[i];
    } else {
        dst[i] = make_float4(0.f, 0.f, 0.f, 0.f);
    }
}

__global__ void mean_kernel(const float* __restrict__ xe, float* __restrict__ xm)
{
    int t = blockIdx.x, c = threadIdx.x;
    float s = 0.0f;
    for (int hw = 0; hw < 256; hw++) s += xe[(size_t)((t << 8) + hw) * 512 + c];
    xm[t * 512 + c] = s * (1.0f / 256.0f);
}

__global__ void scan_kernel(const float* __restrict__ xe, const float* __restrict__ gate,
                            const float* __restrict__ src,
                            const float* __restrict__ lam_re, const float* __restrict__ lam_im,
                            const float* __restrict__ dt,
                            const float2* __restrict__ hprev,
                            float* __restrict__ hrow, float2* __restrict__ lasth)
{
    int e = threadIdx.x;
    int hw = blockIdx.x;
    float lr = lam_re[e], li = lam_im[e];
    float lamr = -(log1pf(expf(lr)) + 0.01f);
    float lami = li;
    float il2 = 1.0f / (lamr * lamr + lami * lami);
    float2 hp = hprev[hw * 256 + e];
    float hr = 0.0f, hi = 0.0f;
    float outr = 0.0f, outi = 0.0f;
    #pragma unroll
    for (int t = 0; t < TSTEPS; t++) {
        float d = dt[t];
        float ed = expf(lamr * d);
        float dr = ed * cosf(lami * d), di = ed * sinf(lami * d);
        float nr = dr - 1.0f;
        float ofr = (nr * lamr + di * lami) * il2;
        float ofi = (di * lamr - nr * lami) * il2;
        int tok = t * 256 + hw;
        float xr = xe[(size_t)tok * 512 + e], xi = xe[(size_t)tok * 512 + 256 + e];
        float g = gate[t * 256 + e];
        float sr = src[t * 512 + e], si = src[t * 512 + 256 + e];
        float fr = xr * g + sr * (1.0f - g);
        float fi = xi * g + si * (1.0f - g);
        float ur = fr * ofr - fi * ofi;
        float ui = fr * ofi + fi * ofr;
        float nhr = dr * hr - di * hi + ur;
        float nhi = dr * hi + di * hr + ui;
        hr = nhr; hi = nhi;
        outr = hr + (hp.x * dr - hp.y * di);
        outi = hi + (hp.x * di + hp.y * dr);
        hrow[(size_t)tok * 512 + e] = outr;
        hrow[(size_t)tok * 512 + 256 + e] = outi;
    }
    lasth[hw * 256 + e] = make_float2(outr, outi);
}

__global__ void probs_kernel(const float* __restrict__ xn, const float* __restrict__ Wr,
                             float* __restrict__ probs)
{
    int gwarp = (blockIdx.x * blockDim.x + threadIdx.x) >> 5;
    int lane = threadIdx.x & 31;
    if (gwarp >= TOK) return;
    const float* x = xn + (size_t)gwarp * 512;
    float l0 = 0, l1 = 0, l2 = 0, l3 = 0;
    for (int k = lane; k < 512; k += 32) {
        float xv = x[k];
        const float* wr = Wr + k * 4;
        l0 += xv * wr[0]; l1 += xv * wr[1]; l2 += xv * wr[2]; l3 += xv * wr[3];
    }
    #pragma unroll
    for (int off = 16; off > 0; off >>= 1) {
        l0 += __shfl_xor_sync(0xffffffffu, l0, off);
        l1 += __shfl_xor_sync(0xffffffffu, l1, off);
        l2 += __shfl_xor_sync(0xffffffffu, l2, off);
        l3 += __shfl_xor_sync(0xffffffffu, l3, off);
    }
    if (lane == 0) {
        float mx = fmaxf(fmaxf(l0, l1), fmaxf(l2, l3));
        float e0 = expf(l0 - mx), e1 = expf(l1 - mx), e2 = expf(l2 - mx), e3 = expf(l3 - mx);
        float inv = 1.0f / (e0 + e1 + e2 + e3);
        probs[gwarp * 4 + 0] = e0 * inv;
        probs[gwarp * 4 + 1] = e1 * inv;
        probs[gwarp * 4 + 2] = e2 * inv;
        probs[gwarp * 4 + 3] = e3 * inv;
    }
}

__global__ void reduce_moe_kernel(const float* __restrict__ x, const float* __restrict__ xn,
                                  const float* __restrict__ oexp, float* __restrict__ z)
{
    int i = blockIdx.x * blockDim.x + threadIdx.x;
    const int n4 = TOK * TWO_D / 4;
    if (i >= n4) return;
    const float4* x4  = (const float4*)x;
    const float4* xn4 = (const float4*)xn;
    const float4* o4  = (const float4*)oexp;
    float4 a = x4[i], b = xn4[i];
    float4 o0 = o4[i], o1 = o4[i + n4], o2 = o4[i + 2 * n4], o3 = o4[i + 3 * n4];
    float4 r;
    r.x = a.x + b.x + o0.x + o1.x + o2.x + o3.x;
    r.y = a.y + b.y + o0.y + o1.y + o2.y + o3.y;
    r.z = a.z + b.z + o0.z + o1.z + o2.z + o3.z;
    r.w = a.w + b.w + o0.w + o1.w + o2.w + o3.w;
    ((float4*)z)[i] = r;
}

__global__ void zero_f2_kernel(float2* p, int n)
{
    int i = blockIdx.x * blockDim.x + threadIdx.x;
    if (i < n) p[i] = make_float2(0.f, 0.f);
}

// ---------------- host orchestration ----------------
template <typename T, size_t N>
static T* sym_addr(const T (&sym)[N]) {
    void* p = nullptr;
    cudaGetSymbolAddress(&p, (const void*)&sym);
    return (T*)p;
}

#define TG_SMEM (4 * 128 * PADK * 2)   // 73728 bytes

extern "C" void kernel_launch(void* const* d_in, const int* in_sizes, int n_in,
                              void* d_out, int out_size)
{
    const float* x      = (const float*)d_in[0];
    const float* dt     = (const float*)d_in[1];
    const float* Wenc   = (const float*)d_in[2];
    const float* benc   = (const float*)d_in[3];
    const float* Wdec   = (const float*)d_in[4];
    const float* bdec   = (const float*)d_in[5];
    const float* ln_sp_w= (const float*)d_in[6];
    const float* ln_sp_b= (const float*)d_in[7];
    const float* conv_w = (const float*)d_in[8];
    const float* conv_b = (const float*)d_in[9];
    const float* E_re   = (const float*)d_in[10];
    const float* E_im   = (const float*)d_in[11];
    const float* Ed_re  = (const float*)d_in[12];
    const float* Ed_im  = (const float*)d_in[13];
    const float* Ws_re  = (const float*)d_in[14];
    const float* Ws_im  = (const float*)d_in[15];
    const float* Wg     = (const float*)d_in[16];
    const float* bg     = (const float*)d_in[17];
    const float* lam_re = (const float*)d_in[18];
    const float* lam_im = (const float*)d_in[19];
    const float* ln_t_w = (const float*)d_in[20];
    const float* ln_t_b = (const float*)d_in[21];
    const float* Wr     = (const float*)d_in[22];
    const float* W1     = (const float*)d_in[23];
    const float* W2     = (const float*)d_in[24];

    float*  p_xp   = sym_addr(g_xp);
    float*  p_z    = sym_addr(g_z);
    float*  p_zn   = sym_addr(g_zn);
    float*  p_col  = sym_addr(g_col);
    float*  p_x    = sym_addr(g_x);
    float*  p_xe   = sym_addr(g_xe);
    float*  p_h    = sym_addr(g_h);
    float*  p_xo   = sym_addr(g_xo);
    float*  p_xn   = sym_addr(g_xn);
    float*  p_hid  = sym_addr(g_hid);
    float*  p_oexp = sym_addr(g_oexp);
    float*  p_yo   = sym_addr(g_yo);
    float*  p_Bp   = sym_addr(g_Bp);
    float*  p_xm   = sym_addr(g_xm);
    float*  p_gate = sym_addr(g_gate);
    float*  p_src  = sym_addr(g_src);
    float*  p_probs= sym_addr(g_probs);
    float2* p_hpA  = sym_addr(g_hpA);
    float2* p_hpB  = sym_addr(g_hpB);
    __nv_bfloat16* p_Ahi = sym_addr(g_Ahi);
    __nv_bfloat16* p_Alo = sym_addr(g_Alo);
    __nv_bfloat16* p_Bhi = sym_addr(g_Bhi);
    __nv_bfloat16* p_Blo = sym_addr(g_Blo);

    cudaFuncSetAttribute(tgemm, cudaFuncAttributeMaxDynamicSharedMemorySize, TG_SMEM);

    // zero h_prev for layer 0
    zero_f2_kernel<<<256, 256>>>(p_hpA, 256 * 256);

    // ---------------- encoder ----------------
    patchify_kernel<<<(TOK * 1024) / 256, 256>>>(x, p_xp);
    split_kernel<<<(TOK * 1024 / 4 + 255) / 256, 256>>>(
        (const float4*)p_xp, (__nv_bfloat162*)p_Ahi, (__nv_bfloat162*)p_Alo, TOK * 1024 / 4);
    tsplit_kernel<<<dim3((512 * 1024 + 255) / 256, 1), 256>>>(
        Wenc, p_Bhi, p_Blo, 1024, 512, 0, 0);
    tgemm<<<dim3(4, 16, 1), 256, TG_SMEM>>>(p_Ahi, p_Alo, p_Bhi, p_Blo, p_z,
                                            TOK, 512, 1024, benc, nullptr, nullptr,
                                            F_BIAS, 0, 0, 0);

    for (int l = 0; l < 2; l++) {
        const float* cE_re  = E_re  + l * 65536;
        const float* cE_im  = E_im  + l * 65536;
        const float* cEd_re = Ed_re + l * 65536;
        const float* cEd_im = Ed_im + l * 65536;
        const float* cWs_re = Ws_re + l * 65536;
        const float* cWs_im = Ws_im + l * 65536;

        // spatial LN
        ln_kernel<<<TOK, 256>>>(p_z, p_zn, ln_sp_w + l * 512, ln_sp_b + l * 512);

        // conv via im2col + tensor GEMM (bias + residual)
        im2col_kernel<<<TOK * 9, 128>>>(p_zn, p_col);
        split_kernel<<<(TOK * KCONV / 4 + 255) / 256, 256>>>(
            (const float4*)p_col, (__nv_bfloat162*)p_Ahi, (__nv_bfloat162*)p_Alo,
            TOK * KCONV / 4);
        conv_w_tsplit<<<(512 * KCONV + 255) / 256, 256>>>(
            conv_w + (size_t)l * 512 * 512 * 9, p_Bhi, p_Blo);
        tgemm<<<dim3(4, 16, 1), 256, TG_SMEM>>>(p_Ahi, p_Alo, p_Bhi, p_Blo, p_x,
                                                TOK, 512, KCONV, conv_b + l * 512, p_z,
                                                nullptr, F_BIAS | F_ADD, 0, 0, 0);

        // x_eigen = x @ E
        split_kernel<<<(TOK * 512 / 4 + 255) / 256, 256>>>(
            (const float4*)p_x, (__nv_bfloat162*)p_Ahi, (__nv_bfloat162*)p_Alo, TOK * 512 / 4);
        pack_cplx_bt<<<1024, 256>>>(cE_re, cE_im, p_Bhi, p_Blo);
        tgemm<<<dim3(4, 16, 1), 256, TG_SMEM>>>(p_Ahi, p_Alo, p_Bhi, p_Blo, p_xe,
                                                TOK, 512, 512, nullptr, nullptr, nullptr,
                                                0, 0, 0, 0);

        // spatial mean -> xm (8 x 512)
        mean_kernel<<<8, 512>>>(p_xe, p_xm);

        // source_seq = xm @ Ws, gate_seq = sigmoid(xm @ Wg + bg)  (tiny, fp32)
        pack_cplx_kernel<<<1024, 256>>>(cWs_re, cWs_im, p_Bp);
        small_mm<<<dim3(4, 8), 128>>>(p_xm, p_Bp, p_src, 8, 512, 512, nullptr, 0);
        small_mm<<<dim3(2, 8), 128>>>(p_xm, Wg + l * 512 * 256, p_gate, 8, 256, 512,
                                      bg + l * 256, 1);

        // temporal scan -> h
        float2* hp_in  = (l == 0) ? p_hpA : p_hpB;
        float2* hp_out = (l == 0) ? p_hpB : p_hpA;
        scan_kernel<<<256, 256>>>(p_xe, p_gate, p_src, lam_re + l * 256, lam_im + l * 256,
                                  dt, hp_in, p_h, hp_out);

        // x_out = h @ Ed
        split_kernel<<<(TOK * 512 / 4 + 255) / 256, 256>>>(
            (const float4*)p_h, (__nv_bfloat162*)p_Ahi, (__nv_bfloat162*)p_Alo, TOK * 512 / 4);
        pack_cplx_bt<<<1024, 256>>>(cEd_re, cEd_im, p_Bhi, p_Blo);
        tgemm<<<dim3(4, 16, 1), 256, TG_SMEM>>>(p_Ahi, p_Alo, p_Bhi, p_Blo, p_xo,
                                                TOK, 512, 512, nullptr, nullptr, nullptr,
                                                0, 0, 0, 0);

        // temporal LN
        ln_kernel<<<TOK, 256>>>(p_xo, p_xn, ln_t_w + l * 512, ln_t_b + l * 512);

        // router probs
        probs_kernel<<<TOK / 8, 256>>>(p_xn, Wr + l * 512 * 4, p_probs);

        // MoE W1: hid[e] = gelu(xn @ W1[e]), batched over experts
        split_kernel<<<(TOK * 512 / 4 + 255) / 256, 256>>>(
            (const float4*)p_xn, (__nv_bfloat162*)p_Ahi, (__nv_bfloat162*)p_Alo, TOK * 512 / 4);
        tsplit_kernel<<<dim3((512 * 1024 + 255) / 256, 4), 256>>>(
            W1 + (size_t)l * 4 * 512 * 1024, p_Bhi, p_Blo, 512, 1024,
            (long)512 * 1024, (long)512 * 1024);
        tgemm<<<dim3(8, 16, 4), 256, TG_SMEM>>>(p_Ahi, p_Alo, p_Bhi, p_Blo, p_hid,
                                                TOK, 1024, 512, nullptr, nullptr, nullptr,
                                                F_GELU, 0, (long)512 * 1024,
                                                (long)TOK * 1024);

        // MoE W2: oexp[e] = probs[:,e] * (hid[e] @ W2[e])
        split_kernel<<<(4 * TOK * 1024 / 4 + 255) / 256, 256>>>(
            (const float4*)p_hid, (__nv_bfloat162*)p_Ahi, (__nv_bfloat162*)p_Alo,
            4 * TOK * 1024 / 4);
        tsplit_kernel<<<dim3((1024 * 512 + 255) / 256, 4), 256>>>(
            W2 + (size_t)l * 4 * 1024 * 512, p_Bhi, p_Blo, 1024, 512,
            (long)1024 * 512, (long)1024 * 512);
        tgemm<<<dim3(4, 16, 4), 256, TG_SMEM>>>(p_Ahi, p_Alo, p_Bhi, p_Blo, p_oexp,
                                                TOK, 512, 1024, nullptr, nullptr, p_probs,
                                                F_SCALE, (long)TOK * 1024,
                                                (long)1024 * 512, (long)TOK * 512);

        // z_next = x + xn + sum_e oexp[e]
        reduce_moe_kernel<<<(TOK * 512 / 4 + 255) / 256, 256>>>(p_x, p_xn, p_oexp, p_z);
    }

    // ---------------- decoder ----------------
    split_kernel<<<(TOK * 512 / 4 + 255) / 256, 256>>>(
        (const float4*)p_z, (__nv_bfloat162*)p_Ahi, (__nv_bfloat162*)p_Alo, TOK * 512 / 4);
    tsplit_kernel<<<dim3((512 * 1024 + 255) / 256, 1), 256>>>(
        Wdec, p_Bhi, p_Blo, 512, 1024, 0, 0);
    tgemm<<<dim3(8, 16, 1), 256, TG_SMEM>>>(p_Ahi, p_Alo, p_Bhi, p_Blo, p_yo,
                                            TOK, 1024, 512, bdec, nullptr, nullptr,
                                            F_BIAS, 0, 0, 0);
    unpatchify_kernel<<<(TOK * 1024) / 256, 256>>>(p_yo, (float*)d_out);
}

// round 5
// speedup vs baseline: 2.0735x; 1.1478x over previous
#include <cuda_runtime.h>
#include <cuda_bf16.h>
#include <math.h>
#include <stdint.h>

// ---------------- problem constants ----------------
#define TOK   2048          // B*T*HP*WP
#define TWO_D 512
#define DDIM  256
#define KCONV 4608          // 512*9
#define TSTEPS 8
#define PADK2 40            // 32 + 8 bf16 row padding (stage width)

// epilogue flags
#define F_BIAS  1
#define F_ADD   2
#define F_GELU  4
#define F_SCALE 8
#define F_SPLIT 16
#define F_NOC   32

// ---------------- device scratch (no allocs allowed) ----------------
__device__ float g_z   [TOK*TWO_D];
__device__ float g_x   [TOK*TWO_D];
__device__ float g_xe  [TOK*TWO_D];
__device__ float g_xo  [TOK*TWO_D];
__device__ float g_xn  [TOK*TWO_D];
__device__ float g_oexp[4*TOK*TWO_D];
__device__ float g_yo  [TOK*1024];
__device__ float g_Bp  [TWO_D*TWO_D];
__device__ float g_xm  [TSTEPS*TWO_D];
__device__ float g_gate[TSTEPS*DDIM];
__device__ float g_src [TSTEPS*TWO_D];
__device__ float g_probs[TOK*4];
__device__ float2 g_hpA[256*256];
__device__ float2 g_hpB[256*256];

// bf16 hi/lo operand buffers
__device__ __nv_bfloat16 g_Ahi[TOK*KCONV];   // big A: col / hid / encoder xp
__device__ __nv_bfloat16 g_Alo[TOK*KCONV];
__device__ __nv_bfloat16 g_A2hi[TOK*1024];   // small A: zn / x / h / xn / z(dec)
__device__ __nv_bfloat16 g_A2lo[TOK*1024];
__device__ __nv_bfloat16 g_Bhi[512*KCONV];   // B weights (N-major)
__device__ __nv_bfloat16 g_Blo[512*KCONV];

// ---------------- helpers ----------------
__device__ __forceinline__ uint32_t smem_to_u32(const void* smem_ptr) {
    uint32_t addr;
    asm("{ .reg .u64 tmp; cvta.to.shared.u64 tmp, %1; cvt.u32.u64 %0, tmp; }"
        : "=r"(addr) : "l"(smem_ptr));
    return addr;
}
__device__ __forceinline__ float gelu_tanh(float x) {
    float x3 = x * x * x;
    return 0.5f * x * (1.0f + tanhf(0.7978845608028654f * (x + 0.044715f * x3)));
}
__device__ __forceinline__ void ldsm_x4(uint32_t* r, uint32_t addr) {
    asm volatile("ldmatrix.sync.aligned.m8n8.x4.shared.b16 {%0,%1,%2,%3}, [%4];"
        : "=r"(r[0]), "=r"(r[1]), "=r"(r[2]), "=r"(r[3]) : "r"(addr));
}
__device__ __forceinline__ void ldsm_x2(uint32_t* r, uint32_t addr) {
    asm volatile("ldmatrix.sync.aligned.m8n8.x2.shared.b16 {%0,%1}, [%2];"
        : "=r"(r[0]), "=r"(r[1]) : "r"(addr));
}
__device__ __forceinline__ void mma_bf16(float* d, const uint32_t* a, const uint32_t* b) {
    asm volatile(
        "mma.sync.aligned.m16n8k16.row.col.f32.bf16.bf16.f32 "
        "{%0,%1,%2,%3}, {%4,%5,%6,%7}, {%8,%9}, {%0,%1,%2,%3};"
        : "+f"(d[0]), "+f"(d[1]), "+f"(d[2]), "+f"(d[3])
        : "r"(a[0]), "r"(a[1]), "r"(a[2]), "r"(a[3]), "r"(b[0]), "r"(b[1]));
}
__device__ __forceinline__ void cpasync16(uint32_t s, const void* g) {
    asm volatile("cp.async.cg.shared.global [%0], [%1], 16;" :: "r"(s), "l"(g));
}
__device__ __forceinline__ void split1(float v, __nv_bfloat16& h, __nv_bfloat16& l) {
    h = __float2bfloat16(v);
    l = __float2bfloat16(v - __bfloat162float(h));
}

// stage layout constants (bytes)
#define MAT_B   (128 * PADK2 * 2)       // 10240
#define STAGE_B (4 * MAT_B)             // 40960
#define TG_SMEM (2 * STAGE_B)           // 81920

// ================= tensor-core GEMM (bf16x3, cp.async double-buffered) =====
// C[M,N] = fp32(A) @ fp32(B); A ≈ Ahi+Alo row-major [M][K]; B N-major [N][K].
// CTA tile 128x128, k-stage 32, 8 warps, warp tile 64x32.
// M%128==0, N%128==0, K%32==0. Batched over blockIdx.z (element strides).
__global__ __launch_bounds__(256, 2)
void tgemm(const __nv_bfloat16* __restrict__ Ahi, const __nv_bfloat16* __restrict__ Alo,
           const __nv_bfloat16* __restrict__ Bhi, const __nv_bfloat16* __restrict__ Blo,
           float* __restrict__ C,
           __nv_bfloat16* __restrict__ Chi, __nv_bfloat16* __restrict__ Clo,
           int M, int N, int K,
           const float* __restrict__ bias,
           const float* __restrict__ add_src,
           const float* __restrict__ probs,
           int flags, long sA, long sB, long sC, long sCh)
{
    extern __shared__ __align__(16) char dsmem[];
    const uint32_t ub = smem_to_u32(dsmem);

    const int tid = threadIdx.x;
    const int wid = tid >> 5;
    const int lane = tid & 31;
    const int warp_m = wid >> 2;       // 0..1 -> 64 rows each
    const int warp_n = wid & 3;        // 0..3 -> 32 cols each

    const int z = blockIdx.z;
    const __nv_bfloat16* Ah = Ahi + (size_t)z * sA;
    const __nv_bfloat16* Al = Alo + (size_t)z * sA;
    const __nv_bfloat16* Bh = Bhi + (size_t)z * sB;
    const __nv_bfloat16* Bl = Blo + (size_t)z * sB;
    const int bm = blockIdx.y * 128;
    const int bn = blockIdx.x * 128;

    float acc[4][4][4];
    #pragma unroll
    for (int i = 0; i < 4; i++)
        #pragma unroll
        for (int j = 0; j < 4; j++)
            #pragma unroll
            for (int q = 0; q < 4; q++) acc[i][j][q] = 0.0f;

    // cp.async mapping: per matrix 128x32 = 512 x (8 bf16); 2 chunks/thread
    const int c0row = tid >> 2;
    const int c0kc  = (tid & 3) * 8;

    const uint32_t aoff = (uint32_t)((warp_m * 64 + (lane & 15)) * PADK2 + (lane >> 4) * 8) * 2;
    const uint32_t boff = (uint32_t)((warp_n * 32 + (lane & 7)) * PADK2 + ((lane >> 3) & 1) * 8) * 2;

    const int NKS = K >> 5;

    // prefetch stage 0
    {
        const uint32_t sb = ub;
        #pragma unroll
        for (int it = 0; it < 2; it++) {
            const int row = c0row + it * 64;
            const uint32_t so = (uint32_t)(row * PADK2 + c0kc) * 2;
            const size_t ga = (size_t)(bm + row) * K + c0kc;
            const size_t gb = (size_t)(bn + row) * K + c0kc;
            cpasync16(sb + so, Ah + ga);
            cpasync16(sb + MAT_B + so, Al + ga);
            cpasync16(sb + 2 * MAT_B + so, Bh + gb);
            cpasync16(sb + 3 * MAT_B + so, Bl + gb);
        }
        asm volatile("cp.async.commit_group;");
    }

    for (int i = 0; i < NKS; i++) {
        asm volatile("cp.async.wait_group 0;");
        __syncthreads();

        if (i + 1 < NKS) {
            const uint32_t sb = ub + ((i + 1) & 1) * STAGE_B;
            const int k0 = (i + 1) << 5;
            #pragma unroll
            for (int it = 0; it < 2; it++) {
                const int row = c0row + it * 64;
                const uint32_t so = (uint32_t)(row * PADK2 + c0kc) * 2;
                const size_t ga = (size_t)(bm + row) * K + k0 + c0kc;
                const size_t gb = (size_t)(bn + row) * K + k0 + c0kc;
                cpasync16(sb + so, Ah + ga);
                cpasync16(sb + MAT_B + so, Al + ga);
                cpasync16(sb + 2 * MAT_B + so, Bh + gb);
                cpasync16(sb + 3 * MAT_B + so, Bl + gb);
            }
            asm volatile("cp.async.commit_group;");
        }

        const uint32_t sb = ub + (i & 1) * STAGE_B;
        #pragma unroll
        for (int ks = 0; ks < 2; ks++) {
            const uint32_t kb = (uint32_t)ks * 32;   // 16 elems * 2B
            uint32_t ah[4][4], al[4][4];
            #pragma unroll
            for (int mi = 0; mi < 4; mi++) {
                const uint32_t ao = sb + aoff + (uint32_t)(mi * 16 * PADK2) * 2 + kb;
                ldsm_x4(ah[mi], ao);
                ldsm_x4(al[mi], ao + MAT_B);
            }
            #pragma unroll
            for (int nj = 0; nj < 4; nj++) {
                const uint32_t bo = sb + 2 * MAT_B + boff + (uint32_t)(nj * 8 * PADK2) * 2 + kb;
                uint32_t bh[2], bl[2];
                ldsm_x2(bh, bo);
                ldsm_x2(bl, bo + MAT_B);
                #pragma unroll
                for (int mi = 0; mi < 4; mi++) {
                    mma_bf16(acc[mi][nj], ah[mi], bh);
                    mma_bf16(acc[mi][nj], ah[mi], bl);
                    mma_bf16(acc[mi][nj], al[mi], bh);
                }
            }
        }
    }

    // epilogue
    float* Cp = C + (size_t)z * sC;
    __nv_bfloat16* Chp = Chi + (size_t)z * sCh;
    __nv_bfloat16* Clp = Clo + (size_t)z * sCh;
    #pragma unroll
    for (int mi = 0; mi < 4; mi++) {
        #pragma unroll
        for (int nj = 0; nj < 4; nj++) {
            const int m0 = bm + warp_m * 64 + mi * 16 + (lane >> 2);
            const int n0 = bn + warp_n * 32 + nj * 8 + (lane & 3) * 2;
            float v00 = acc[mi][nj][0], v01 = acc[mi][nj][1];
            float v10 = acc[mi][nj][2], v11 = acc[mi][nj][3];
            if (flags & F_BIAS) {
                const float2 bb = *(const float2*)&bias[n0];
                v00 += bb.x; v01 += bb.y; v10 += bb.x; v11 += bb.y;
            }
            if (flags & F_ADD) {
                const float2 r0 = *(const float2*)&add_src[(size_t)m0 * N + n0];
                const float2 r1 = *(const float2*)&add_src[(size_t)(m0 + 8) * N + n0];
                v00 += r0.x; v01 += r0.y; v10 += r1.x; v11 += r1.y;
            }
            if (flags & F_GELU) {
                v00 = gelu_tanh(v00); v01 = gelu_tanh(v01);
                v10 = gelu_tanh(v10); v11 = gelu_tanh(v11);
            }
            if (flags & F_SCALE) {
                const float s0 = probs[(size_t)m0 * 4 + z];
                const float s1 = probs[(size_t)(m0 + 8) * 4 + z];
                v00 *= s0; v01 *= s0; v10 *= s1; v11 *= s1;
            }
            if (!(flags & F_NOC)) {
                float2 o0; o0.x = v00; o0.y = v01;
                float2 o1; o1.x = v10; o1.y = v11;
                *(float2*)&Cp[(size_t)m0 * N + n0] = o0;
                *(float2*)&Cp[(size_t)(m0 + 8) * N + n0] = o1;
            }
            if (flags & F_SPLIT) {
                __nv_bfloat16 h0, l0, h1, l1, h2, l2, h3, l3;
                split1(v00, h0, l0); split1(v01, h1, l1);
                split1(v10, h2, l2); split1(v11, h3, l3);
                *(__nv_bfloat162*)&Chp[(size_t)m0 * N + n0] = __halves2bfloat162(h0, h1);
                *(__nv_bfloat162*)&Clp[(size_t)m0 * N + n0] = __halves2bfloat162(l0, l1);
                *(__nv_bfloat162*)&Chp[(size_t)(m0 + 8) * N + n0] = __halves2bfloat162(h2, h3);
                *(__nv_bfloat162*)&Clp[(size_t)(m0 + 8) * N + n0] = __halves2bfloat162(l2, l3);
            }
        }
    }
}

// ================= producers emitting bf16 hi/lo directly =================
// patchify + split: x (1,8,4,256,256) -> hi/lo (2048, 1024)
__global__ void patchify_split(const float* __restrict__ x,
                               __nv_bfloat16* __restrict__ hi,
                               __nv_bfloat16* __restrict__ lo)
{
    int idx = blockIdx.x * blockDim.x + threadIdx.x;
    if (idx >= TOK * 1024) return;
    int tok = idx >> 10, k = idx & 1023;
    int t = tok >> 8, hp = (tok >> 4) & 15, wp = tok & 15;
    int c = k >> 8, py = (k >> 4) & 15, px = k & 15;
    float v = x[(((size_t)(t * 4 + c) * 256) + hp * 16 + py) * 256 + wp * 16 + px];
    split1(v, hi[idx], lo[idx]);
}

// LayerNorm; optional fp32 out Yf, always bf16 hi/lo out
__global__ void ln_split(const float* __restrict__ X, float* __restrict__ Yf,
                         __nv_bfloat16* __restrict__ Yh, __nv_bfloat16* __restrict__ Yl,
                         const float* __restrict__ w, const float* __restrict__ b)
{
    __shared__ float sh[256];
    int tok = blockIdx.x, tid = threadIdx.x;
    const float* x = X + (size_t)tok * 512;
    float v1 = x[tid], v2 = x[tid + 256];
    sh[tid] = v1 + v2;
    __syncthreads();
    for (int s = 128; s > 0; s >>= 1) { if (tid < s) sh[tid] += sh[tid + s]; __syncthreads(); }
    float mean = sh[0] * (1.0f / 512.0f);
    __syncthreads();
    float d1 = v1 - mean, d2 = v2 - mean;
    sh[tid] = d1 * d1 + d2 * d2;
    __syncthreads();
    for (int s = 128; s > 0; s >>= 1) { if (tid < s) sh[tid] += sh[tid + s]; __syncthreads(); }
    float rstd = rsqrtf(sh[0] * (1.0f / 512.0f) + 1e-5f);
    float y1 = d1 * rstd * w[tid] + b[tid];
    float y2 = d2 * rstd * w[tid + 256] + b[tid + 256];
    size_t o1 = (size_t)tok * 512 + tid, o2 = o1 + 256;
    if (Yf) { Yf[o1] = y1; Yf[o2] = y2; }
    split1(y1, Yh[o1], Yl[o1]);
    split1(y2, Yh[o2], Yl[o2]);
}

// im2col on bf16 hi/lo: col[tok][pos*512+ic] from zn hi/lo (token-major 512)
__global__ void im2col_bf16(const __nv_bfloat16* __restrict__ znh,
                            const __nv_bfloat16* __restrict__ znl,
                            __nv_bfloat16* __restrict__ colh,
                            __nv_bfloat16* __restrict__ coll)
{
    int bid = blockIdx.x;
    int tok = bid / 9, pos = bid - tok * 9;
    int t = tok >> 8, hw = tok & 255;
    int y = hw >> 4, x = hw & 15;
    int ny = y + pos / 3 - 1, nx = x + pos % 3 - 1;
    int i = threadIdx.x;  // 0..63, each 8 bf16 (16B)
    uint4* dh = (uint4*)(colh + (size_t)tok * KCONV + pos * 512);
    uint4* dl = (uint4*)(coll + (size_t)tok * KCONV + pos * 512);
    if ((unsigned)ny < 16u && (unsigned)nx < 16u) {
        const size_t src = (size_t)(t * 256 + ny * 16 + nx) * 512;
        dh[i] = ((const uint4*)(znh + src))[i];
        dl[i] = ((const uint4*)(znl + src))[i];
    } else {
        uint4 zr = make_uint4(0, 0, 0, 0);
        dh[i] = zr;
        dl[i] = zr;
    }
}

// fp32 -> bf16 hi/lo split (decoder input only)
__global__ void split_kernel(const float4* __restrict__ src,
                             __nv_bfloat162* __restrict__ hi,
                             __nv_bfloat162* __restrict__ lo, int n4)
{
    int i = blockIdx.x * blockDim.x + threadIdx.x;
    if (i >= n4) return;
    float4 v = src[i];
    __nv_bfloat16 h0, l0, h1, l1, h2, l2, h3, l3;
    split1(v.x, h0, l0); split1(v.y, h1, l1);
    split1(v.z, h2, l2); split1(v.w, h3, l3);
    hi[2 * i]     = __halves2bfloat162(h0, h1);
    hi[2 * i + 1] = __halves2bfloat162(h2, h3);
    lo[2 * i]     = __halves2bfloat162(l0, l1);
    lo[2 * i + 1] = __halves2bfloat162(l2, l3);
}

// transpose + split: out[z][n*K+k] = src[z*sSrc + k*N + n]
__global__ void tsplit_kernel(const float* __restrict__ src,
                              __nv_bfloat16* __restrict__ hi,
                              __nv_bfloat16* __restrict__ lo,
                              int K, int N, long sSrc, long sDst)
{
    long idx = (long)blockIdx.x * blockDim.x + threadIdx.x;
    long total = (long)K * N;
    if (idx >= total) return;
    int z = blockIdx.y;
    int n = (int)(idx / K);
    int k = (int)(idx - (long)n * K);
    float v = src[(size_t)z * sSrc + (size_t)k * N + n];
    split1(v, hi[(size_t)z * sDst + idx], lo[(size_t)z * sDst + idx]);
}

// pack complex (Re,Im 256x256) -> Bt[n][k] of the 512x512 block matrix, split
__global__ void pack_cplx_bt(const float* __restrict__ Re, const float* __restrict__ Im,
                             __nv_bfloat16* __restrict__ hi, __nv_bfloat16* __restrict__ lo)
{
    int idx = blockIdx.x * blockDim.x + threadIdx.x;
    if (idx >= 512 * 512) return;
    int n = idx >> 9, k = idx & 511;
    float v;
    if (k < 256) v = (n < 256) ? Re[k * 256 + n] : Im[k * 256 + (n - 256)];
    else {
        int d = k - 256;
        v = (n < 256) ? -Im[d * 256 + n] : Re[d * 256 + (n - 256)];
    }
    split1(v, hi[idx], lo[idx]);
}

// conv weights (512,512,3,3) -> Bt[oc][pos*512+ic], split
__global__ void conv_w_tsplit(const float* __restrict__ cw,
                              __nv_bfloat16* __restrict__ hi, __nv_bfloat16* __restrict__ lo)
{
    int idx = blockIdx.x * blockDim.x + threadIdx.x;
    if (idx >= 512 * KCONV) return;
    int oc = idx / KCONV, kk = idx - oc * KCONV;
    int ic = kk & 511, pos = kk >> 9;
    int ky = pos / 3, kx = pos - ky * 3;
    float v = cw[(((size_t)oc * 512 + ic) * 3 + ky) * 3 + kx];
    split1(v, hi[idx], lo[idx]);
}

// ================= elementwise / small kernels =================
__global__ void small_mm(const float* __restrict__ A, const float* __restrict__ B,
                         float* __restrict__ C, int M, int N, int K,
                         const float* __restrict__ bias, int act)
{
    int n = blockIdx.x * blockDim.x + threadIdx.x;
    int m = blockIdx.y;
    if (n >= N || m >= M) return;
    float acc = 0.0f;
    for (int k = 0; k < K; k++) acc += A[m * K + k] * B[k * N + n];
    if (bias) acc += bias[n];
    if (act == 1) acc = 1.0f / (1.0f + expf(-acc));
    C[m * N + n] = acc;
}

__global__ void unpatchify_kernel(const float* __restrict__ yo, float* __restrict__ out)
{
    int idx = blockIdx.x * blockDim.x + threadIdx.x;
    if (idx >= TOK * 1024) return;
    int iw = idx & 255, ih = (idx >> 8) & 255, c = (idx >> 16) & 3, t = idx >> 18;
    int hp = ih >> 4, py = ih & 15, wp = iw >> 4, px = iw & 15;
    int tok = (t << 8) + hp * 16 + wp;
    out[idx] = yo[(size_t)tok * 1024 + c * 256 + py * 16 + px];
}

// fp32 pack (only for the tiny small_mm path, Ws)
__global__ void pack_cplx_kernel(const float* __restrict__ Re, const float* __restrict__ Im,
                                 float* __restrict__ Bp)
{
    int idx = blockIdx.x * blockDim.x + threadIdx.x;
    if (idx >= 512 * 512) return;
    int k = idx >> 9, n = idx & 511;
    float v;
    if (k < 256) v = (n < 256) ? Re[k * 256 + n] : Im[k * 256 + (n - 256)];
    else {
        int d = k - 256;
        v = (n < 256) ? -Im[d * 256 + n] : Re[d * 256 + (n - 256)];
    }
    Bp[idx] = v;
}

__global__ void mean_kernel(const float* __restrict__ xe, float* __restrict__ xm)
{
    int t = blockIdx.x, c = threadIdx.x;
    float s = 0.0f;
    for (int hw = 0; hw < 256; hw++) s += xe[(size_t)((t << 8) + hw) * 512 + c];
    xm[t * 512 + c] = s * (1.0f / 256.0f);
}

// temporal recurrence per (hw, e); emits h as bf16 hi/lo (GEMM A operand)
__global__ void scan_kernel(const float* __restrict__ xe, const float* __restrict__ gate,
                            const float* __restrict__ src,
                            const float* __restrict__ lam_re, const float* __restrict__ lam_im,
                            const float* __restrict__ dt,
                            const float2* __restrict__ hprev,
                            __nv_bfloat16* __restrict__ hh, __nv_bfloat16* __restrict__ hl,
                            float2* __restrict__ lasth)
{
    int e = threadIdx.x;
    int hw = blockIdx.x;
    float lr = lam_re[e], li = lam_im[e];
    float lamr = -(log1pf(expf(lr)) + 0.01f);
    float lami = li;
    float il2 = 1.0f / (lamr * lamr + lami * lami);
    float2 hp = hprev[hw * 256 + e];
    float hr = 0.0f, hi = 0.0f;
    float outr = 0.0f, outi = 0.0f;
    #pragma unroll
    for (int t = 0; t < TSTEPS; t++) {
        float d = dt[t];
        float ed = expf(lamr * d);
        float dr = ed * cosf(lami * d), di = ed * sinf(lami * d);
        float nr = dr - 1.0f;
        float ofr = (nr * lamr + di * lami) * il2;
        float ofi = (di * lamr - nr * lami) * il2;
        int tok = t * 256 + hw;
        float xr = xe[(size_t)tok * 512 + e], xi = xe[(size_t)tok * 512 + 256 + e];
        float g = gate[t * 256 + e];
        float sr = src[t * 512 + e], si = src[t * 512 + 256 + e];
        float fr = xr * g + sr * (1.0f - g);
        float fi = xi * g + si * (1.0f - g);
        float ur = fr * ofr - fi * ofi;
        float ui = fr * ofi + fi * ofr;
        float nhr = dr * hr - di * hi + ur;
        float nhi = dr * hi + di * hr + ui;
        hr = nhr; hi = nhi;
        outr = hr + (hp.x * dr - hp.y * di);
        outi = hi + (hp.x * di + hp.y * dr);
        size_t o1 = (size_t)tok * 512 + e, o2 = o1 + 256;
        split1(outr, hh[o1], hl[o1]);
        split1(outi, hh[o2], hl[o2]);
    }
    lasth[hw * 256 + e] = make_float2(outr, outi);
}

__global__ void probs_kernel(const float* __restrict__ xn, const float* __restrict__ Wr,
                             float* __restrict__ probs)
{
    int gwarp = (blockIdx.x * blockDim.x + threadIdx.x) >> 5;
    int lane = threadIdx.x & 31;
    if (gwarp >= TOK) return;
    const float* x = xn + (size_t)gwarp * 512;
    float l0 = 0, l1 = 0, l2 = 0, l3 = 0;
    for (int k = lane; k < 512; k += 32) {
        float xv = x[k];
        const float* wr = Wr + k * 4;
        l0 += xv * wr[0]; l1 += xv * wr[1]; l2 += xv * wr[2]; l3 += xv * wr[3];
    }
    #pragma unroll
    for (int off = 16; off > 0; off >>= 1) {
        l0 += __shfl_xor_sync(0xffffffffu, l0, off);
        l1 += __shfl_xor_sync(0xffffffffu, l1, off);
        l2 += __shfl_xor_sync(0xffffffffu, l2, off);
        l3 += __shfl_xor_sync(0xffffffffu, l3, off);
    }
    if (lane == 0) {
        float mx = fmaxf(fmaxf(l0, l1), fmaxf(l2, l3));
        float e0 = expf(l0 - mx), e1 = expf(l1 - mx), e2 = expf(l2 - mx), e3 = expf(l3 - mx);
        float inv = 1.0f / (e0 + e1 + e2 + e3);
        probs[gwarp * 4 + 0] = e0 * inv;
        probs[gwarp * 4 + 1] = e1 * inv;
        probs[gwarp * 4 + 2] = e2 * inv;
        probs[gwarp * 4 + 3] = e3 * inv;
    }
}

__global__ void reduce_moe_kernel(const float* __restrict__ x, const float* __restrict__ xn,
                                  const float* __restrict__ oexp, float* __restrict__ z)
{
    int i = blockIdx.x * blockDim.x + threadIdx.x;
    const int n4 = TOK * TWO_D / 4;
    if (i >= n4) return;
    const float4* x4  = (const float4*)x;
    const float4* xn4 = (const float4*)xn;
    const float4* o4  = (const float4*)oexp;
    float4 a = x4[i], b = xn4[i];
    float4 o0 = o4[i], o1 = o4[i + n4], o2 = o4[i + 2 * n4], o3 = o4[i + 3 * n4];
    float4 r;
    r.x = a.x + b.x + o0.x + o1.x + o2.x + o3.x;
    r.y = a.y + b.y + o0.y + o1.y + o2.y + o3.y;
    r.z = a.z + b.z + o0.z + o1.z + o2.z + o3.z;
    r.w = a.w + b.w + o0.w + o1.w + o2.w + o3.w;
    ((float4*)z)[i] = r;
}

__global__ void zero_f2_kernel(float2* p, int n)
{
    int i = blockIdx.x * blockDim.x + threadIdx.x;
    if (i < n) p[i] = make_float2(0.f, 0.f);
}

// ---------------- host orchestration ----------------
template <typename T, size_t N>
static T* sym_addr(const T (&sym)[N]) {
    void* p = nullptr;
    cudaGetSymbolAddress(&p, (const void*)&sym);
    return (T*)p;
}

extern "C" void kernel_launch(void* const* d_in, const int* in_sizes, int n_in,
                              void* d_out, int out_size)
{
    const float* x      = (const float*)d_in[0];
    const float* dt     = (const float*)d_in[1];
    const float* Wenc   = (const float*)d_in[2];
    const float* benc   = (const float*)d_in[3];
    const float* Wdec   = (const float*)d_in[4];
    const float* bdec   = (const float*)d_in[5];
    const float* ln_sp_w= (const float*)d_in[6];
    const float* ln_sp_b= (const float*)d_in[7];
    const float* conv_w = (const float*)d_in[8];
    const float* conv_b = (const float*)d_in[9];
    const float* E_re   = (const float*)d_in[10];
    const float* E_im   = (const float*)d_in[11];
    const float* Ed_re  = (const float*)d_in[12];
    const float* Ed_im  = (const float*)d_in[13];
    const float* Ws_re  = (const float*)d_in[14];
    const float* Ws_im  = (const float*)d_in[15];
    const float* Wg     = (const float*)d_in[16];
    const float* bg     = (const float*)d_in[17];
    const float* lam_re = (const float*)d_in[18];
    const float* lam_im = (const float*)d_in[19];
    const float* ln_t_w = (const float*)d_in[20];
    const float* ln_t_b = (const float*)d_in[21];
    const float* Wr     = (const float*)d_in[22];
    const float* W1     = (const float*)d_in[23];
    const float* W2     = (const float*)d_in[24];

    float*  p_z    = sym_addr(g_z);
    float*  p_x    = sym_addr(g_x);
    float*  p_xe   = sym_addr(g_xe);
    float*  p_xo   = sym_addr(g_xo);
    float*  p_xn   = sym_addr(g_xn);
    float*  p_oexp = sym_addr(g_oexp);
    float*  p_yo   = sym_addr(g_yo);
    float*  p_Bp   = sym_addr(g_Bp);
    float*  p_xm   = sym_addr(g_xm);
    float*  p_gate = sym_addr(g_gate);
    float*  p_src  = sym_addr(g_src);
    float*  p_probs= sym_addr(g_probs);
    float2* p_hpA  = sym_addr(g_hpA);
    float2* p_hpB  = sym_addr(g_hpB);
    __nv_bfloat16* p_Ahi  = sym_addr(g_Ahi);
    __nv_bfloat16* p_Alo  = sym_addr(g_Alo);
    __nv_bfloat16* p_A2hi = sym_addr(g_A2hi);
    __nv_bfloat16* p_A2lo = sym_addr(g_A2lo);
    __nv_bfloat16* p_Bhi  = sym_addr(g_Bhi);
    __nv_bfloat16* p_Blo  = sym_addr(g_Blo);

    cudaFuncSetAttribute(tgemm, cudaFuncAttributeMaxDynamicSharedMemorySize, TG_SMEM);

    // zero h_prev for layer 0
    zero_f2_kernel<<<256, 256>>>(p_hpA, 256 * 256);

    // ---------------- encoder ----------------
    patchify_split<<<(TOK * 1024) / 256, 256>>>(x, p_Ahi, p_Alo);
    tsplit_kernel<<<dim3((512 * 1024 + 255) / 256, 1), 256>>>(
        Wenc, p_Bhi, p_Blo, 1024, 512, 0, 0);
    tgemm<<<dim3(4, 16, 1), 256, TG_SMEM>>>(p_Ahi, p_Alo, p_Bhi, p_Blo, p_z,
                                            p_A2hi, p_A2lo, TOK, 512, 1024,
                                            benc, nullptr, nullptr, F_BIAS, 0, 0, 0, 0);

    for (int l = 0; l < 2; l++) {
        const float* cE_re  = E_re  + l * 65536;
        const float* cE_im  = E_im  + l * 65536;
        const float* cEd_re = Ed_re + l * 65536;
        const float* cEd_im = Ed_im + l * 65536;
        const float* cWs_re = Ws_re + l * 65536;
        const float* cWs_im = Ws_im + l * 65536;

        // spatial LN -> zn hi/lo only
        ln_split<<<TOK, 256>>>(p_z, nullptr, p_A2hi, p_A2lo,
                               ln_sp_w + l * 512, ln_sp_b + l * 512);

        // conv: bf16 im2col + GEMM, epilogue = bias + residual, fp32 x + hi/lo x
        im2col_bf16<<<TOK * 9, 64>>>(p_A2hi, p_A2lo, p_Ahi, p_Alo);
        conv_w_tsplit<<<(512 * KCONV + 255) / 256, 256>>>(
            conv_w + (size_t)l * 512 * 512 * 9, p_Bhi, p_Blo);
        tgemm<<<dim3(4, 16, 1), 256, TG_SMEM>>>(p_Ahi, p_Alo, p_Bhi, p_Blo, p_x,
                                                p_A2hi, p_A2lo, TOK, 512, KCONV,
                                                conv_b + l * 512, p_z, nullptr,
                                                F_BIAS | F_ADD | F_SPLIT, 0, 0, 0, 0);

        // x_eigen = x @ E   (A = x hi/lo from conv epilogue)
        pack_cplx_bt<<<1024, 256>>>(cE_re, cE_im, p_Bhi, p_Blo);
        tgemm<<<dim3(4, 16, 1), 256, TG_SMEM>>>(p_A2hi, p_A2lo, p_Bhi, p_Blo, p_xe,
                                                nullptr, nullptr, TOK, 512, 512,
                                                nullptr, nullptr, nullptr, 0, 0, 0, 0, 0);

        // spatial mean -> xm (8 x 512)
        mean_kernel<<<8, 512>>>(p_xe, p_xm);

        // source_seq = xm @ Ws, gate_seq = sigmoid(xm @ Wg + bg)  (tiny, fp32)
        pack_cplx_kernel<<<1024, 256>>>(cWs_re, cWs_im, p_Bp);
        small_mm<<<dim3(4, 8), 128>>>(p_xm, p_Bp, p_src, 8, 512, 512, nullptr, 0);
        small_mm<<<dim3(2, 8), 128>>>(p_xm, Wg + l * 512 * 256, p_gate, 8, 256, 512,
                                      bg + l * 256, 1);

        // temporal scan -> h hi/lo (GEMM A operand)
        float2* hp_in  = (l == 0) ? p_hpA : p_hpB;
        float2* hp_out = (l == 0) ? p_hpB : p_hpA;
        scan_kernel<<<256, 256>>>(p_xe, p_gate, p_src, lam_re + l * 256, lam_im + l * 256,
                                  dt, hp_in, p_A2hi, p_A2lo, hp_out);

        // x_out = h @ Ed
        pack_cplx_bt<<<1024, 256>>>(cEd_re, cEd_im, p_Bhi, p_Blo);
        tgemm<<<dim3(4, 16, 1), 256, TG_SMEM>>>(p_A2hi, p_A2lo, p_Bhi, p_Blo, p_xo,
                                                nullptr, nullptr, TOK, 512, 512,
                                                nullptr, nullptr, nullptr, 0, 0, 0, 0, 0);

        // temporal LN -> xn fp32 + hi/lo
        ln_split<<<TOK, 256>>>(p_xo, p_xn, p_A2hi, p_A2lo,
                               ln_t_w + l * 512, ln_t_b + l * 512);

        // router probs (fp32 xn)
        probs_kernel<<<TOK / 8, 256>>>(p_xn, Wr + l * 512 * 4, p_probs);

        // MoE W1: hid[e] = gelu(xn @ W1[e]) -> hi/lo only, batched over experts
        tsplit_kernel<<<dim3((512 * 1024 + 255) / 256, 4), 256>>>(
            W1 + (size_t)l * 4 * 512 * 1024, p_Bhi, p_Blo, 512, 1024,
            (long)512 * 1024, (long)512 * 1024);
        tgemm<<<dim3(8, 16, 4), 256, TG_SMEM>>>(p_A2hi, p_A2lo, p_Bhi, p_Blo, nullptr,
                                                p_Ahi, p_Alo, TOK, 1024, 512,
                                                nullptr, nullptr, nullptr,
                                                F_GELU | F_SPLIT | F_NOC,
                                                0, (long)512 * 1024, 0, (long)TOK * 1024);

        // MoE W2: oexp[e] = probs[:,e] * (hid[e] @ W2[e])
        tsplit_kernel<<<dim3((1024 * 512 + 255) / 256, 4), 256>>>(
            W2 + (size_t)l * 4 * 1024 * 512, p_Bhi, p_Blo, 1024, 512,
            (long)1024 * 512, (long)1024 * 512);
        tgemm<<<dim3(4, 16, 4), 256, TG_SMEM>>>(p_Ahi, p_Alo, p_Bhi, p_Blo, p_oexp,
                                                nullptr, nullptr, TOK, 512, 1024,
                                                nullptr, nullptr, p_probs, F_SCALE,
                                                (long)TOK * 1024, (long)1024 * 512,
                                                (long)TOK * 512, 0);

        // z_next = x + xn + sum_e oexp[e]
        reduce_moe_kernel<<<(TOK * 512 / 4 + 255) / 256, 256>>>(p_x, p_xn, p_oexp, p_z);
    }

    // ---------------- decoder ----------------
    split_kernel<<<(TOK * 512 / 4 + 255) / 256, 256>>>(
        (const float4*)p_z, (__nv_bfloat162*)p_A2hi, (__nv_bfloat162*)p_A2lo, TOK * 512 / 4);
    tsplit_kernel<<<dim3((512 * 1024 + 255) / 256, 1), 256>>>(
        Wdec, p_Bhi, p_Blo, 512, 1024, 0, 0);
    tgemm<<<dim3(8, 16, 1), 256, TG_SMEM>>>(p_A2hi, p_A2lo, p_Bhi, p_Blo, p_yo,
                                            nullptr, nullptr, TOK, 1024, 512,
                                            bdec, nullptr, nullptr, F_BIAS, 0, 0, 0, 0);
    unpatchify_kernel<<<(TOK * 1024) / 256, 256>>>(p_yo, (float*)d_out);
}

// round 6
// speedup vs baseline: 2.4831x; 1.1975x over previous
#include <cuda_runtime.h>
#include <cuda_bf16.h>
#include <math.h>
#include <stdint.h>

// ---------------- problem constants ----------------
#define TOK   2048          // B*T*HP*WP
#define TWO_D 512
#define DDIM  256
#define KCONV 4608          // 512*9
#define TSTEPS 8
#define PADK2 40            // 32 + 8 bf16 row padding (stage width)

// epilogue flags
#define F_BIAS  1
#define F_ADD   2
#define F_GELU  4
#define F_SCALE 8
#define F_SPLIT 16
#define F_NOC   32

// ---------------- device scratch (no allocs allowed) ----------------
__device__ float g_z   [TOK*TWO_D];
__device__ float g_x   [TOK*TWO_D];
__device__ float g_xe  [TOK*TWO_D];
__device__ float g_xo  [TOK*TWO_D];
__device__ float g_xn  [TOK*TWO_D];
__device__ float g_oexp[4*TOK*TWO_D];
__device__ float g_yo  [TOK*1024];
__device__ float g_Bp  [TWO_D*TWO_D];
__device__ float g_xm  [TSTEPS*TWO_D];
__device__ float g_gate[TSTEPS*DDIM];
__device__ float g_src [TSTEPS*TWO_D];
__device__ float g_probs[TOK*4];
__device__ float2 g_hpA[256*256];
__device__ float2 g_hpB[256*256];

// bf16 hi/lo operand buffers
__device__ __nv_bfloat16 g_Ahi[TOK*KCONV];   // big A: col / hid
__device__ __nv_bfloat16 g_Alo[TOK*KCONV];
__device__ __nv_bfloat16 g_A2hi[TOK*1024];   // small A: zn / x / h / xn / z(dec)
__device__ __nv_bfloat16 g_A2lo[TOK*1024];
__device__ __nv_bfloat16 g_Bhi[512*KCONV];   // B weights (N-major)
__device__ __nv_bfloat16 g_Blo[512*KCONV];

// ---------------- helpers ----------------
__device__ __forceinline__ uint32_t smem_to_u32(const void* smem_ptr) {
    uint32_t addr;
    asm("{ .reg .u64 tmp; cvta.to.shared.u64 tmp, %1; cvt.u32.u64 %0, tmp; }"
        : "=r"(addr) : "l"(smem_ptr));
    return addr;
}
__device__ __forceinline__ float gelu_tanh(float x) {
    float x3 = x * x * x;
    return 0.5f * x * (1.0f + tanhf(0.7978845608028654f * (x + 0.044715f * x3)));
}
__device__ __forceinline__ void ldsm_x4(uint32_t* r, uint32_t addr) {
    asm volatile("ldmatrix.sync.aligned.m8n8.x4.shared.b16 {%0,%1,%2,%3}, [%4];"
        : "=r"(r[0]), "=r"(r[1]), "=r"(r[2]), "=r"(r[3]) : "r"(addr));
}
__device__ __forceinline__ void ldsm_x2(uint32_t* r, uint32_t addr) {
    asm volatile("ldmatrix.sync.aligned.m8n8.x2.shared.b16 {%0,%1}, [%2];"
        : "=r"(r[0]), "=r"(r[1]) : "r"(addr));
}
__device__ __forceinline__ void mma_bf16(float* d, const uint32_t* a, const uint32_t* b) {
    asm volatile(
        "mma.sync.aligned.m16n8k16.row.col.f32.bf16.bf16.f32 "
        "{%0,%1,%2,%3}, {%4,%5,%6,%7}, {%8,%9}, {%0,%1,%2,%3};"
        : "+f"(d[0]), "+f"(d[1]), "+f"(d[2]), "+f"(d[3])
        : "r"(a[0]), "r"(a[1]), "r"(a[2]), "r"(a[3]), "r"(b[0]), "r"(b[1]));
}
__device__ __forceinline__ void cpasync16(uint32_t s, const void* g) {
    asm volatile("cp.async.cg.shared.global [%0], [%1], 16;" :: "r"(s), "l"(g));
}
__device__ __forceinline__ void split1(float v, __nv_bfloat16& h, __nv_bfloat16& l) {
    h = __float2bfloat16(v);
    l = __float2bfloat16(v - __bfloat162float(h));
}

// stage layout constants (bytes): 64-row tiles
#define MAT_B   (64 * PADK2 * 2)        // 5120
#define STAGE_B (4 * MAT_B)             // 20480
#define TG_SMEM (2 * STAGE_B)           // 40960

// ================= tensor-core GEMM (bf16x3, cp.async double-buffered) =====
// C[M,N] = fp32(A) @ fp32(B); A ≈ Ahi+Alo row-major [M][K]; B N-major [N][K].
// CTA tile 64x64, k-stage 32, 4 warps (2x2), warp tile 32x32.
// M%64==0, N%64==0, K%32==0. Batched over blockIdx.z (element strides).
__global__ __launch_bounds__(128, 4)
void tgemm(const __nv_bfloat16* __restrict__ Ahi, const __nv_bfloat16* __restrict__ Alo,
           const __nv_bfloat16* __restrict__ Bhi, const __nv_bfloat16* __restrict__ Blo,
           float* __restrict__ C,
           __nv_bfloat16* __restrict__ Chi, __nv_bfloat16* __restrict__ Clo,
           int M, int N, int K,
           const float* __restrict__ bias,
           const float* __restrict__ add_src,
           const float* __restrict__ probs,
           int flags, long sA, long sB, long sC, long sCh)
{
    extern __shared__ __align__(16) char dsmem[];
    const uint32_t ub = smem_to_u32(dsmem);

    const int tid = threadIdx.x;
    const int wid = tid >> 5;
    const int lane = tid & 31;
    const int warp_m = wid >> 1;       // 0..1 -> 32 rows each
    const int warp_n = wid & 1;        // 0..1 -> 32 cols each

    const int z = blockIdx.z;
    const __nv_bfloat16* Ah = Ahi + (size_t)z * sA;
    const __nv_bfloat16* Al = Alo + (size_t)z * sA;
    const __nv_bfloat16* Bh = Bhi + (size_t)z * sB;
    const __nv_bfloat16* Bl = Blo + (size_t)z * sB;
    const int bm = blockIdx.y * 64;
    const int bn = blockIdx.x * 64;

    float acc[2][4][4];
    #pragma unroll
    for (int i = 0; i < 2; i++)
        #pragma unroll
        for (int j = 0; j < 4; j++)
            #pragma unroll
            for (int q = 0; q < 4; q++) acc[i][j][q] = 0.0f;

    // cp.async mapping: per matrix 64x32 bf16 = 256 x 16B chunks; 2 per thread
    const int c0row = tid >> 2;        // 0..31 (+32)
    const int c0kc  = (tid & 3) * 8;

    const uint32_t aoff = (uint32_t)((warp_m * 32 + (lane & 15)) * PADK2 + (lane >> 4) * 8) * 2;
    const uint32_t boff = (uint32_t)((warp_n * 32 + (lane & 7)) * PADK2 + ((lane >> 3) & 1) * 8) * 2;

    const int NKS = K >> 5;

    // prefetch stage 0
    {
        const uint32_t sb = ub;
        #pragma unroll
        for (int it = 0; it < 2; it++) {
            const int row = c0row + it * 32;
            const uint32_t so = (uint32_t)(row * PADK2 + c0kc) * 2;
            const size_t ga = (size_t)(bm + row) * K + c0kc;
            const size_t gb = (size_t)(bn + row) * K + c0kc;
            cpasync16(sb + so, Ah + ga);
            cpasync16(sb + MAT_B + so, Al + ga);
            cpasync16(sb + 2 * MAT_B + so, Bh + gb);
            cpasync16(sb + 3 * MAT_B + so, Bl + gb);
        }
        asm volatile("cp.async.commit_group;");
    }

    for (int i = 0; i < NKS; i++) {
        asm volatile("cp.async.wait_group 0;");
        __syncthreads();

        if (i + 1 < NKS) {
            const uint32_t sb = ub + ((i + 1) & 1) * STAGE_B;
            const int k0 = (i + 1) << 5;
            #pragma unroll
            for (int it = 0; it < 2; it++) {
                const int row = c0row + it * 32;
                const uint32_t so = (uint32_t)(row * PADK2 + c0kc) * 2;
                const size_t ga = (size_t)(bm + row) * K + k0 + c0kc;
                const size_t gb = (size_t)(bn + row) * K + k0 + c0kc;
                cpasync16(sb + so, Ah + ga);
                cpasync16(sb + MAT_B + so, Al + ga);
                cpasync16(sb + 2 * MAT_B + so, Bh + gb);
                cpasync16(sb + 3 * MAT_B + so, Bl + gb);
            }
            asm volatile("cp.async.commit_group;");
        }

        const uint32_t sb = ub + (i & 1) * STAGE_B;
        #pragma unroll
        for (int ks = 0; ks < 2; ks++) {
            const uint32_t kb = (uint32_t)ks * 32;   // 16 elems * 2B
            uint32_t ah[2][4], al[2][4];
            #pragma unroll
            for (int mi = 0; mi < 2; mi++) {
                const uint32_t ao = sb + aoff + (uint32_t)(mi * 16 * PADK2) * 2 + kb;
                ldsm_x4(ah[mi], ao);
                ldsm_x4(al[mi], ao + MAT_B);
            }
            #pragma unroll
            for (int nj = 0; nj < 4; nj++) {
                const uint32_t bo = sb + 2 * MAT_B + boff + (uint32_t)(nj * 8 * PADK2) * 2 + kb;
                uint32_t bh[2], bl[2];
                ldsm_x2(bh, bo);
                ldsm_x2(bl, bo + MAT_B);
                #pragma unroll
                for (int mi = 0; mi < 2; mi++) {
                    mma_bf16(acc[mi][nj], ah[mi], bh);
                    mma_bf16(acc[mi][nj], ah[mi], bl);
                    mma_bf16(acc[mi][nj], al[mi], bh);
                }
            }
        }
    }

    // epilogue
    float* Cp = C + (size_t)z * sC;
    __nv_bfloat16* Chp = Chi + (size_t)z * sCh;
    __nv_bfloat16* Clp = Clo + (size_t)z * sCh;
    #pragma unroll
    for (int mi = 0; mi < 2; mi++) {
        #pragma unroll
        for (int nj = 0; nj < 4; nj++) {
            const int m0 = bm + warp_m * 32 + mi * 16 + (lane >> 2);
            const int n0 = bn + warp_n * 32 + nj * 8 + (lane & 3) * 2;
            float v00 = acc[mi][nj][0], v01 = acc[mi][nj][1];
            float v10 = acc[mi][nj][2], v11 = acc[mi][nj][3];
            if (flags & F_BIAS) {
                const float2 bb = *(const float2*)&bias[n0];
                v00 += bb.x; v01 += bb.y; v10 += bb.x; v11 += bb.y;
            }
            if (flags & F_ADD) {
                const float2 r0 = *(const float2*)&add_src[(size_t)m0 * N + n0];
                const float2 r1 = *(const float2*)&add_src[(size_t)(m0 + 8) * N + n0];
                v00 += r0.x; v01 += r0.y; v10 += r1.x; v11 += r1.y;
            }
            if (flags & F_GELU) {
                v00 = gelu_tanh(v00); v01 = gelu_tanh(v01);
                v10 = gelu_tanh(v10); v11 = gelu_tanh(v11);
            }
            if (flags & F_SCALE) {
                const float s0 = probs[(size_t)m0 * 4 + z];
                const float s1 = probs[(size_t)(m0 + 8) * 4 + z];
                v00 *= s0; v01 *= s0; v10 *= s1; v11 *= s1;
            }
            if (!(flags & F_NOC)) {
                float2 o0; o0.x = v00; o0.y = v01;
                float2 o1; o1.x = v10; o1.y = v11;
                *(float2*)&Cp[(size_t)m0 * N + n0] = o0;
                *(float2*)&Cp[(size_t)(m0 + 8) * N + n0] = o1;
            }
            if (flags & F_SPLIT) {
                __nv_bfloat16 h0, l0, h1, l1, h2, l2, h3, l3;
                split1(v00, h0, l0); split1(v01, h1, l1);
                split1(v10, h2, l2); split1(v11, h3, l3);
                *(__nv_bfloat162*)&Chp[(size_t)m0 * N + n0] = __halves2bfloat162(h0, h1);
                *(__nv_bfloat162*)&Clp[(size_t)m0 * N + n0] = __halves2bfloat162(l0, l1);
                *(__nv_bfloat162*)&Chp[(size_t)(m0 + 8) * N + n0] = __halves2bfloat162(h2, h3);
                *(__nv_bfloat162*)&Clp[(size_t)(m0 + 8) * N + n0] = __halves2bfloat162(l2, l3);
            }
        }
    }
}

// ================= producers emitting bf16 hi/lo directly =================
__global__ void patchify_split(const float* __restrict__ x,
                               __nv_bfloat16* __restrict__ hi,
                               __nv_bfloat16* __restrict__ lo)
{
    int idx = blockIdx.x * blockDim.x + threadIdx.x;
    if (idx >= TOK * 1024) return;
    int tok = idx >> 10, k = idx & 1023;
    int t = tok >> 8, hp = (tok >> 4) & 15, wp = tok & 15;
    int c = k >> 8, py = (k >> 4) & 15, px = k & 15;
    float v = x[(((size_t)(t * 4 + c) * 256) + hp * 16 + py) * 256 + wp * 16 + px];
    split1(v, hi[idx], lo[idx]);
}

__global__ void ln_split(const float* __restrict__ X, float* __restrict__ Yf,
                         __nv_bfloat16* __restrict__ Yh, __nv_bfloat16* __restrict__ Yl,
                         const float* __restrict__ w, const float* __restrict__ b)
{
    __shared__ float sh[256];
    int tok = blockIdx.x, tid = threadIdx.x;
    const float* x = X + (size_t)tok * 512;
    float v1 = x[tid], v2 = x[tid + 256];
    sh[tid] = v1 + v2;
    __syncthreads();
    for (int s = 128; s > 0; s >>= 1) { if (tid < s) sh[tid] += sh[tid + s]; __syncthreads(); }
    float mean = sh[0] * (1.0f / 512.0f);
    __syncthreads();
    float d1 = v1 - mean, d2 = v2 - mean;
    sh[tid] = d1 * d1 + d2 * d2;
    __syncthreads();
    for (int s = 128; s > 0; s >>= 1) { if (tid < s) sh[tid] += sh[tid + s]; __syncthreads(); }
    float rstd = rsqrtf(sh[0] * (1.0f / 512.0f) + 1e-5f);
    float y1 = d1 * rstd * w[tid] + b[tid];
    float y2 = d2 * rstd * w[tid + 256] + b[tid + 256];
    size_t o1 = (size_t)tok * 512 + tid, o2 = o1 + 256;
    if (Yf) { Yf[o1] = y1; Yf[o2] = y2; }
    split1(y1, Yh[o1], Yl[o1]);
    split1(y2, Yh[o2], Yl[o2]);
}

__global__ void im2col_bf16(const __nv_bfloat16* __restrict__ znh,
                            const __nv_bfloat16* __restrict__ znl,
                            __nv_bfloat16* __restrict__ colh,
                            __nv_bfloat16* __restrict__ coll)
{
    int bid = blockIdx.x;
    int tok = bid / 9, pos = bid - tok * 9;
    int t = tok >> 8, hw = tok & 255;
    int y = hw >> 4, x = hw & 15;
    int ny = y + pos / 3 - 1, nx = x + pos % 3 - 1;
    int i = threadIdx.x;  // 0..63, each 8 bf16 (16B)
    uint4* dh = (uint4*)(colh + (size_t)tok * KCONV + pos * 512);
    uint4* dl = (uint4*)(coll + (size_t)tok * KCONV + pos * 512);
    if ((unsigned)ny < 16u && (unsigned)nx < 16u) {
        const size_t src = (size_t)(t * 256 + ny * 16 + nx) * 512;
        dh[i] = ((const uint4*)(znh + src))[i];
        dl[i] = ((const uint4*)(znl + src))[i];
    } else {
        uint4 zr = make_uint4(0, 0, 0, 0);
        dh[i] = zr;
        dl[i] = zr;
    }
}

__global__ void split_kernel(const float4* __restrict__ src,
                             __nv_bfloat162* __restrict__ hi,
                             __nv_bfloat162* __restrict__ lo, int n4)
{
    int i = blockIdx.x * blockDim.x + threadIdx.x;
    if (i >= n4) return;
    float4 v = src[i];
    __nv_bfloat16 h0, l0, h1, l1, h2, l2, h3, l3;
    split1(v.x, h0, l0); split1(v.y, h1, l1);
    split1(v.z, h2, l2); split1(v.w, h3, l3);
    hi[2 * i]     = __halves2bfloat162(h0, h1);
    hi[2 * i + 1] = __halves2bfloat162(h2, h3);
    lo[2 * i]     = __halves2bfloat162(l0, l1);
    lo[2 * i + 1] = __halves2bfloat162(l2, l3);
}

__global__ void tsplit_kernel(const float* __restrict__ src,
                              __nv_bfloat16* __restrict__ hi,
                              __nv_bfloat16* __restrict__ lo,
                              int K, int N, long sSrc, long sDst)
{
    long idx = (long)blockIdx.x * blockDim.x + threadIdx.x;
    long total = (long)K * N;
    if (idx >= total) return;
    int z = blockIdx.y;
    int n = (int)(idx / K);
    int k = (int)(idx - (long)n * K);
    float v = src[(size_t)z * sSrc + (size_t)k * N + n];
    split1(v, hi[(size_t)z * sDst + idx], lo[(size_t)z * sDst + idx]);
}

__global__ void pack_cplx_bt(const float* __restrict__ Re, const float* __restrict__ Im,
                             __nv_bfloat16* __restrict__ hi, __nv_bfloat16* __restrict__ lo)
{
    int idx = blockIdx.x * blockDim.x + threadIdx.x;
    if (idx >= 512 * 512) return;
    int n = idx >> 9, k = idx & 511;
    float v;
    if (k < 256) v = (n < 256) ? Re[k * 256 + n] : Im[k * 256 + (n - 256)];
    else {
        int d = k - 256;
        v = (n < 256) ? -Im[d * 256 + n] : Re[d * 256 + (n - 256)];
    }
    split1(v, hi[idx], lo[idx]);
}

__global__ void conv_w_tsplit(const float* __restrict__ cw,
                              __nv_bfloat16* __restrict__ hi, __nv_bfloat16* __restrict__ lo)
{
    int idx = blockIdx.x * blockDim.x + threadIdx.x;
    if (idx >= 512 * KCONV) return;
    int oc = idx / KCONV, kk = idx - oc * KCONV;
    int ic = kk & 511, pos = kk >> 9;
    int ky = pos / 3, kx = pos - ky * 3;
    float v = cw[(((size_t)oc * 512 + ic) * 3 + ky) * 3 + kx];
    split1(v, hi[idx], lo[idx]);
}

// ================= elementwise / small kernels =================
__global__ void small_mm(const float* __restrict__ A, const float* __restrict__ B,
                         float* __restrict__ C, int M, int N, int K,
                         const float* __restrict__ bias, int act)
{
    int n = blockIdx.x * blockDim.x + threadIdx.x;
    int m = blockIdx.y;
    if (n >= N || m >= M) return;
    float acc = 0.0f;
    for (int k = 0; k < K; k++) acc += A[m * K + k] * B[k * N + n];
    if (bias) acc += bias[n];
    if (act == 1) acc = 1.0f / (1.0f + expf(-acc));
    C[m * N + n] = acc;
}

__global__ void unpatchify_kernel(const float* __restrict__ yo, float* __restrict__ out)
{
    int idx = blockIdx.x * blockDim.x + threadIdx.x;
    if (idx >= TOK * 1024) return;
    int iw = idx & 255, ih = (idx >> 8) & 255, c = (idx >> 16) & 3, t = idx >> 18;
    int hp = ih >> 4, py = ih & 15, wp = iw >> 4, px = iw & 15;
    int tok = (t << 8) + hp * 16 + wp;
    out[idx] = yo[(size_t)tok * 1024 + c * 256 + py * 16 + px];
}

__global__ void pack_cplx_kernel(const float* __restrict__ Re, const float* __restrict__ Im,
                                 float* __restrict__ Bp)
{
    int idx = blockIdx.x * blockDim.x + threadIdx.x;
    if (idx >= 512 * 512) return;
    int k = idx >> 9, n = idx & 511;
    float v;
    if (k < 256) v = (n < 256) ? Re[k * 256 + n] : Im[k * 256 + (n - 256)];
    else {
        int d = k - 256;
        v = (n < 256) ? -Im[d * 256 + n] : Re[d * 256 + (n - 256)];
    }
    Bp[idx] = v;
}

__global__ void mean_kernel(const float* __restrict__ xe, float* __restrict__ xm)
{
    int t = blockIdx.x, c = threadIdx.x;
    float s = 0.0f;
    for (int hw = 0; hw < 256; hw++) s += xe[(size_t)((t << 8) + hw) * 512 + c];
    xm[t * 512 + c] = s * (1.0f / 256.0f);
}

__global__ void scan_kernel(const float* __restrict__ xe, const float* __restrict__ gate,
                            const float* __restrict__ src,
                            const float* __restrict__ lam_re, const float* __restrict__ lam_im,
                            const float* __restrict__ dt,
                            const float2* __restrict__ hprev,
                            __nv_bfloat16* __restrict__ hh, __nv_bfloat16* __restrict__ hl,
                            float2* __restrict__ lasth)
{
    int e = threadIdx.x;
    int hw = blockIdx.x;
    float lr = lam_re[e], li = lam_im[e];
    float lamr = -(log1pf(expf(lr)) + 0.01f);
    float lami = li;
    float il2 = 1.0f / (lamr * lamr + lami * lami);
    float2 hp = hprev[hw * 256 + e];
    float hr = 0.0f, hi = 0.0f;
    float outr = 0.0f, outi = 0.0f;
    #pragma unroll
    for (int t = 0; t < TSTEPS; t++) {
        float d = dt[t];
        float ed = expf(lamr * d);
        float dr = ed * cosf(lami * d), di = ed * sinf(lami * d);
        float nr = dr - 1.0f;
        float ofr = (nr * lamr + di * lami) * il2;
        float ofi = (di * lamr - nr * lami) * il2;
        int tok = t * 256 + hw;
        float xr = xe[(size_t)tok * 512 + e], xi = xe[(size_t)tok * 512 + 256 + e];
        float g = gate[t * 256 + e];
        float sr = src[t * 512 + e], si = src[t * 512 + 256 + e];
        float fr = xr * g + sr * (1.0f - g);
        float fi = xi * g + si * (1.0f - g);
        float ur = fr * ofr - fi * ofi;
        float ui = fr * ofi + fi * ofr;
        float nhr = dr * hr - di * hi + ur;
        float nhi = dr * hi + di * hr + ui;
        hr = nhr; hi = nhi;
        outr = hr + (hp.x * dr - hp.y * di);
        outi = hi + (hp.x * di + hp.y * dr);
        size_t o1 = (size_t)tok * 512 + e, o2 = o1 + 256;
        split1(outr, hh[o1], hl[o1]);
        split1(outi, hh[o2], hl[o2]);
    }
    lasth[hw * 256 + e] = make_float2(outr, outi);
}

__global__ void probs_kernel(const float* __restrict__ xn, const float* __restrict__ Wr,
                             float* __restrict__ probs)
{
    int gwarp = (blockIdx.x * blockDim.x + threadIdx.x) >> 5;
    int lane = threadIdx.x & 31;
    if (gwarp >= TOK) return;
    const float* x = xn + (size_t)gwarp * 512;
    float l0 = 0, l1 = 0, l2 = 0, l3 = 0;
    for (int k = lane; k < 512; k += 32) {
        float xv = x[k];
        const float* wr = Wr + k * 4;
        l0 += xv * wr[0]; l1 += xv * wr[1]; l2 += xv * wr[2]; l3 += xv * wr[3];
    }
    #pragma unroll
    for (int off = 16; off > 0; off >>= 1) {
        l0 += __shfl_xor_sync(0xffffffffu, l0, off);
        l1 += __shfl_xor_sync(0xffffffffu, l1, off);
        l2 += __shfl_xor_sync(0xffffffffu, l2, off);
        l3 += __shfl_xor_sync(0xffffffffu, l3, off);
    }
    if (lane == 0) {
        float mx = fmaxf(fmaxf(l0, l1), fmaxf(l2, l3));
        float e0 = expf(l0 - mx), e1 = expf(l1 - mx), e2 = expf(l2 - mx), e3 = expf(l3 - mx);
        float inv = 1.0f / (e0 + e1 + e2 + e3);
        probs[gwarp * 4 + 0] = e0 * inv;
        probs[gwarp * 4 + 1] = e1 * inv;
        probs[gwarp * 4 + 2] = e2 * inv;
        probs[gwarp * 4 + 3] = e3 * inv;
    }
}

__global__ void reduce_moe_kernel(const float* __restrict__ x, const float* __restrict__ xn,
                                  const float* __restrict__ oexp, float* __restrict__ z)
{
    int i = blockIdx.x * blockDim.x + threadIdx.x;
    const int n4 = TOK * TWO_D / 4;
    if (i >= n4) return;
    const float4* x4  = (const float4*)x;
    const float4* xn4 = (const float4*)xn;
    const float4* o4  = (const float4*)oexp;
    float4 a = x4[i], b = xn4[i];
    float4 o0 = o4[i], o1 = o4[i + n4], o2 = o4[i + 2 * n4], o3 = o4[i + 3 * n4];
    float4 r;
    r.x = a.x + b.x + o0.x + o1.x + o2.x + o3.x;
    r.y = a.y + b.y + o0.y + o1.y + o2.y + o3.y;
    r.z = a.z + b.z + o0.z + o1.z + o2.z + o3.z;
    r.w = a.w + b.w + o0.w + o1.w + o2.w + o3.w;
    ((float4*)z)[i] = r;
}

__global__ void zero_f2_kernel(float2* p, int n)
{
    int i = blockIdx.x * blockDim.x + threadIdx.x;
    if (i < n) p[i] = make_float2(0.f, 0.f);
}

// ---------------- host orchestration ----------------
template <typename T, size_t N>
static T* sym_addr(const T (&sym)[N]) {
    void* p = nullptr;
    cudaGetSymbolAddress(&p, (const void*)&sym);
    return (T*)p;
}

extern "C" void kernel_launch(void* const* d_in, const int* in_sizes, int n_in,
                              void* d_out, int out_size)
{
    const float* x      = (const float*)d_in[0];
    const float* dt     = (const float*)d_in[1];
    const float* Wenc   = (const float*)d_in[2];
    const float* benc   = (const float*)d_in[3];
    const float* Wdec   = (const float*)d_in[4];
    const float* bdec   = (const float*)d_in[5];
    const float* ln_sp_w= (const float*)d_in[6];
    const float* ln_sp_b= (const float*)d_in[7];
    const float* conv_w = (const float*)d_in[8];
    const float* conv_b = (const float*)d_in[9];
    const float* E_re   = (const float*)d_in[10];
    const float* E_im   = (const float*)d_in[11];
    const float* Ed_re  = (const float*)d_in[12];
    const float* Ed_im  = (const float*)d_in[13];
    const float* Ws_re  = (const float*)d_in[14];
    const float* Ws_im  = (const float*)d_in[15];
    const float* Wg     = (const float*)d_in[16];
    const float* bg     = (const float*)d_in[17];
    const float* lam_re = (const float*)d_in[18];
    const float* lam_im = (const float*)d_in[19];
    const float* ln_t_w = (const float*)d_in[20];
    const float* ln_t_b = (const float*)d_in[21];
    const float* Wr     = (const float*)d_in[22];
    const float* W1     = (const float*)d_in[23];
    const float* W2     = (const float*)d_in[24];

    float*  p_z    = sym_addr(g_z);
    float*  p_x    = sym_addr(g_x);
    float*  p_xe   = sym_addr(g_xe);
    float*  p_xo   = sym_addr(g_xo);
    float*  p_xn   = sym_addr(g_xn);
    float*  p_oexp = sym_addr(g_oexp);
    float*  p_yo   = sym_addr(g_yo);
    float*  p_Bp   = sym_addr(g_Bp);
    float*  p_xm   = sym_addr(g_xm);
    float*  p_gate = sym_addr(g_gate);
    float*  p_src  = sym_addr(g_src);
    float*  p_probs= sym_addr(g_probs);
    float2* p_hpA  = sym_addr(g_hpA);
    float2* p_hpB  = sym_addr(g_hpB);
    __nv_bfloat16* p_Ahi  = sym_addr(g_Ahi);
    __nv_bfloat16* p_Alo  = sym_addr(g_Alo);
    __nv_bfloat16* p_A2hi = sym_addr(g_A2hi);
    __nv_bfloat16* p_A2lo = sym_addr(g_A2lo);
    __nv_bfloat16* p_Bhi  = sym_addr(g_Bhi);
    __nv_bfloat16* p_Blo  = sym_addr(g_Blo);

    cudaFuncSetAttribute(tgemm, cudaFuncAttributeMaxDynamicSharedMemorySize, TG_SMEM);

    // zero h_prev for layer 0
    zero_f2_kernel<<<256, 256>>>(p_hpA, 256 * 256);

    // ---------------- encoder ----------------
    patchify_split<<<(TOK * 1024) / 256, 256>>>(x, p_Ahi, p_Alo);
    tsplit_kernel<<<dim3((512 * 1024 + 255) / 256, 1), 256>>>(
        Wenc, p_Bhi, p_Blo, 1024, 512, 0, 0);
    tgemm<<<dim3(8, 32, 1), 128, TG_SMEM>>>(p_Ahi, p_Alo, p_Bhi, p_Blo, p_z,
                                            p_A2hi, p_A2lo, TOK, 512, 1024,
                                            benc, nullptr, nullptr, F_BIAS, 0, 0, 0, 0);

    for (int l = 0; l < 2; l++) {
        const float* cE_re  = E_re  + l * 65536;
        const float* cE_im  = E_im  + l * 65536;
        const float* cEd_re = Ed_re + l * 65536;
        const float* cEd_im = Ed_im + l * 65536;
        const float* cWs_re = Ws_re + l * 65536;
        const float* cWs_im = Ws_im + l * 65536;

        // spatial LN -> zn hi/lo only
        ln_split<<<TOK, 256>>>(p_z, nullptr, p_A2hi, p_A2lo,
                               ln_sp_w + l * 512, ln_sp_b + l * 512);

        // conv: bf16 im2col + GEMM, epilogue = bias + residual, fp32 x + hi/lo x
        im2col_bf16<<<TOK * 9, 64>>>(p_A2hi, p_A2lo, p_Ahi, p_Alo);
        conv_w_tsplit<<<(512 * KCONV + 255) / 256, 256>>>(
            conv_w + (size_t)l * 512 * 512 * 9, p_Bhi, p_Blo);
        tgemm<<<dim3(8, 32, 1), 128, TG_SMEM>>>(p_Ahi, p_Alo, p_Bhi, p_Blo, p_x,
                                                p_A2hi, p_A2lo, TOK, 512, KCONV,
                                                conv_b + l * 512, p_z, nullptr,
                                                F_BIAS | F_ADD | F_SPLIT, 0, 0, 0, 0);

        // x_eigen = x @ E   (A = x hi/lo from conv epilogue)
        pack_cplx_bt<<<1024, 256>>>(cE_re, cE_im, p_Bhi, p_Blo);
        tgemm<<<dim3(8, 32, 1), 128, TG_SMEM>>>(p_A2hi, p_A2lo, p_Bhi, p_Blo, p_xe,
                                                nullptr, nullptr, TOK, 512, 512,
                                                nullptr, nullptr, nullptr, 0, 0, 0, 0, 0);

        // spatial mean -> xm (8 x 512)
        mean_kernel<<<8, 512>>>(p_xe, p_xm);

        // source_seq = xm @ Ws, gate_seq = sigmoid(xm @ Wg + bg)  (tiny, fp32)
        pack_cplx_kernel<<<1024, 256>>>(cWs_re, cWs_im, p_Bp);
        small_mm<<<dim3(4, 8), 128>>>(p_xm, p_Bp, p_src, 8, 512, 512, nullptr, 0);
        small_mm<<<dim3(2, 8), 128>>>(p_xm, Wg + l * 512 * 256, p_gate, 8, 256, 512,
                                      bg + l * 256, 1);

        // temporal scan -> h hi/lo (GEMM A operand)
        float2* hp_in  = (l == 0) ? p_hpA : p_hpB;
        float2* hp_out = (l == 0) ? p_hpB : p_hpA;
        scan_kernel<<<256, 256>>>(p_xe, p_gate, p_src, lam_re + l * 256, lam_im + l * 256,
                                  dt, hp_in, p_A2hi, p_A2lo, hp_out);

        // x_out = h @ Ed
        pack_cplx_bt<<<1024, 256>>>(cEd_re, cEd_im, p_Bhi, p_Blo);
        tgemm<<<dim3(8, 32, 1), 128, TG_SMEM>>>(p_A2hi, p_A2lo, p_Bhi, p_Blo, p_xo,
                                                nullptr, nullptr, TOK, 512, 512,
                                                nullptr, nullptr, nullptr, 0, 0, 0, 0, 0);

        // temporal LN -> xn fp32 + hi/lo
        ln_split<<<TOK, 256>>>(p_xo, p_xn, p_A2hi, p_A2lo,
                               ln_t_w + l * 512, ln_t_b + l * 512);

        // router probs (fp32 xn)
        probs_kernel<<<TOK / 8, 256>>>(p_xn, Wr + l * 512 * 4, p_probs);

        // MoE W1: hid[e] = gelu(xn @ W1[e]) -> hi/lo only, batched over experts
        tsplit_kernel<<<dim3((512 * 1024 + 255) / 256, 4), 256>>>(
            W1 + (size_t)l * 4 * 512 * 1024, p_Bhi, p_Blo, 512, 1024,
            (long)512 * 1024, (long)512 * 1024);
        tgemm<<<dim3(16, 32, 4), 128, TG_SMEM>>>(p_A2hi, p_A2lo, p_Bhi, p_Blo, nullptr,
                                                 p_Ahi, p_Alo, TOK, 1024, 512,
                                                 nullptr, nullptr, nullptr,
                                                 F_GELU | F_SPLIT | F_NOC,
                                                 0, (long)512 * 1024, 0, (long)TOK * 1024);

        // MoE W2: oexp[e] = probs[:,e] * (hid[e] @ W2[e])
        tsplit_kernel<<<dim3((1024 * 512 + 255) / 256, 4), 256>>>(
            W2 + (size_t)l * 4 * 1024 * 512, p_Bhi, p_Blo, 1024, 512,
            (long)1024 * 512, (long)1024 * 512);
        tgemm<<<dim3(8, 32, 4), 128, TG_SMEM>>>(p_Ahi, p_Alo, p_Bhi, p_Blo, p_oexp,
                                                nullptr, nullptr, TOK, 512, 1024,
                                                nullptr, nullptr, p_probs, F_SCALE,
                                                (long)TOK * 1024, (long)1024 * 512,
                                                (long)TOK * 512, 0);

        // z_next = x + xn + sum_e oexp[e]
        reduce_moe_kernel<<<(TOK * 512 / 4 + 255) / 256, 256>>>(p_x, p_xn, p_oexp, p_z);
    }

    // ---------------- decoder ----------------
    split_kernel<<<(TOK * 512 / 4 + 255) / 256, 256>>>(
        (const float4*)p_z, (__nv_bfloat162*)p_A2hi, (__nv_bfloat162*)p_A2lo, TOK * 512 / 4);
    tsplit_kernel<<<dim3((512 * 1024 + 255) / 256, 1), 256>>>(
        Wdec, p_Bhi, p_Blo, 512, 1024, 0, 0);
    tgemm<<<dim3(16, 32, 1), 128, TG_SMEM>>>(p_A2hi, p_A2lo, p_Bhi, p_Blo, p_yo,
                                             nullptr, nullptr, TOK, 1024, 512,
                                             bdec, nullptr, nullptr, F_BIAS, 0, 0, 0, 0);
    unpatchify_kernel<<<(TOK * 1024) / 256, 256>>>(p_yo, (float*)d_out);
}